// round 9
// baseline (speedup 1.0000x reference)
#include <cuda_runtime.h>
#include <math.h>

#define BB 4
#define CC 3
#define HH 384
#define WW 384
#define HWs (HH*WW)
#define NBC 12
#define NTOT (NBC*HWs)
#define NBE (CC*HWs)
#define IRK 16
#define NP_CORR 216   // corr11 blocks per batch (6*12*3)
#define NP_UPD  108   // update2 blocks per batch

// ------------ static device scratch ------------
__device__ float d_b[NTOT];
__device__ float d_r[NTOT];
__device__ float d_p[NTOT];
__device__ float d_Ap[NTOT];
__device__ float d_t1[NTOT];
__device__ float d_t2[NTOT];
__device__ float d_wreg[(size_t)IRK * NTOT];
__device__ float d_part[BB * 512];
__device__ float d_scal[16]; // [0..3]=rs [4..7]=alpha [8..11]=beta [12..15]=active
__device__ float d_S[162];   // [0..80]=S_data  [81..161]=S_reg
__device__ int   d_cnt[8];   // completion counters (self-resetting)
__device__ volatile int d_flag[4];

__device__ __forceinline__ float warpRed(float v) {
#pragma unroll
    for (int o = 16; o > 0; o >>= 1) v += __shfl_down_sync(0xffffffffu, v, o);
    return v;
}

// Block-reduce s, store partial, detect last block of batch b, then cooperatively
// reduce all nblk partials. Returns true on ALL threads of the last block.
__device__ __forceinline__ bool lastBlockTotal(int tid, float s, int b, int slot,
                                               int nblk, float* tot) {
    __shared__ float sm[8];
    __shared__ int lastF;
    float w = warpRed(s);
    if ((tid & 31) == 0) sm[tid >> 5] = w;
    __syncthreads();
    if (tid == 0) {
        float v = 0;
#pragma unroll
        for (int i = 0; i < 8; i++) v += sm[i];
        d_part[b * 512 + slot] = v;
        __threadfence();
        int old = atomicAdd(&d_cnt[b], 1);
        lastF = (old == nblk - 1);
        if (lastF) d_cnt[b] = 0;
    }
    __syncthreads();
    if (!lastF) return false;
    float t = 0;
    for (int i = tid; i < nblk; i += 256) t += d_part[b * 512 + i];
    t = warpRed(t);
    __syncthreads();
    if ((tid & 31) == 0) sm[tid >> 5] = t;
    __syncthreads();
    float v = 0;
#pragma unroll
    for (int i = 0; i < 8; i++) v += sm[i];
    *tot = v;
    return true;
}

// ------- build composed 9x9 kernels S(d) = sum_i kw_i sum_e k_i(e) k_i(e+d) -------
__global__ void autocorr_k(const float* __restrict__ dks, const float* __restrict__ dkw,
                           const float* __restrict__ rks, const float* __restrict__ rkw)
{
    int tid = threadIdx.x;
    if (tid < 162) {
        int which = tid / 81, t = tid % 81;
        const float* ks = which ? rks : dks;
        const float* kw = which ? rkw : dkw;
        int I = which ? 16 : 8;
        int dy = t / 9 - 4, dx = t % 9 - 4;
        float s = 0.f;
        for (int i = 0; i < I; i++) {
            float w = kw[i];
            for (int u = 0; u < 5; u++)
                for (int v = 0; v < 5; v++) {
                    int u2 = u + dy, v2 = v + dx;
                    if (u2 >= 0 && u2 < 5 && v2 >= 0 && v2 < 5)
                        s += w * ks[i * 25 + u * 5 + v] * ks[i * 25 + u2 * 5 + v2];
                }
        }
        d_S[which * 81 + t] = s;
    }
}

// ---------------- 11x11 per-batch correlation, SAME, zero pad ----------------
// 64x32 tile, block (32,8). thread tx covers cols tx and tx+32.
// mode 0: out = acc
// mode 1: out += acc; fused dot(out_new, dv); last block computes alpha/active
// mode 2: Ap = out+acc; rv=b-Ap; r=p=rv; fused rs; last block stores rs
__global__ __launch_bounds__(256)
void corr11_k(const float* __restrict__ in, float* __restrict__ out,
              const float* __restrict__ kern, int flip, int mode,
              const float* __restrict__ dv)
{
    __shared__ float tile[42 * 74];
    __shared__ float sk[121];
    const int bc = blockIdx.z;
    const int bat = bc / CC;
    const float* ip = in + (size_t)bc * HWs;
    const int tid = threadIdx.y * 32 + threadIdx.x;
    if (tid < 121) sk[tid] = kern[bat * 121 + (flip ? 120 - tid : tid)];
    const int X0 = blockIdx.x * 64, Y0 = blockIdx.y * 32;
    for (int k = tid; k < 42 * 74; k += 256) {
        int sy = k / 74, sx = k % 74;
        int gy = Y0 - 5 + sy, gx = X0 - 5 + sx;
        tile[k] = (gy >= 0 && gy < HH && gx >= 0 && gx < WW) ? ip[gy * WW + gx] : 0.f;
    }
    __syncthreads();
    const int ry = threadIdx.y * 4;
    const int tx = threadIdx.x;
    float acc0[4] = {0, 0, 0, 0}, acc1[4] = {0, 0, 0, 0};
#pragma unroll
    for (int a = 0; a < 11; a++) {
        float kc[11];
#pragma unroll
        for (int u = 0; u < 11; u++) kc[u] = sk[u * 11 + a];
#pragma unroll
        for (int rr = 0; rr < 14; rr++) {
            float v0 = tile[(ry + rr) * 74 + tx + a];
            float v1 = tile[(ry + rr) * 74 + tx + 32 + a];
#pragma unroll
            for (int k = 0; k < 4; k++) {
                int u = rr - k;
                if (u >= 0 && u <= 10) {
                    acc0[k] += v0 * kc[u];
                    acc1[k] += v1 * kc[u];
                }
            }
        }
    }
    size_t obase = (size_t)bc * HWs + (size_t)(Y0 + ry) * WW + X0 + tx;
    if (mode == 0) {
#pragma unroll
        for (int k = 0; k < 4; k++) {
            out[obase + (size_t)k * WW] = acc0[k];
            out[obase + (size_t)k * WW + 32] = acc1[k];
        }
        return;
    }
    float s = 0.f;
    if (mode == 1) {
#pragma unroll
        for (int k = 0; k < 4; k++) {
            size_t o = obase + (size_t)k * WW;
            float a0 = out[o] + acc0[k]; out[o] = a0; s += a0 * dv[o];
            size_t o1 = o + 32;
            float a1 = out[o1] + acc1[k]; out[o1] = a1; s += a1 * dv[o1];
        }
    } else {
#pragma unroll
        for (int k = 0; k < 4; k++) {
            size_t o = obase + (size_t)k * WW;
            float a0 = out[o] + acc0[k];
            float rv0 = d_b[o] - a0; d_r[o] = rv0; d_p[o] = rv0; s += rv0 * rv0;
            size_t o1 = o + 32;
            float a1 = out[o1] + acc1[k];
            float rv1 = d_b[o1] - a1; d_r[o1] = rv1; d_p[o1] = rv1; s += rv1 * rv1;
        }
    }
    int slot = (bc % CC) * 72 + blockIdx.y * 6 + blockIdx.x;
    float tot;
    if (lastBlockTotal(tid, s, bat, slot, NP_CORR, &tot)) {
        if (tid == 0) {
            if (mode == 2) {
                d_scal[bat] = tot;                 // rs
            } else {
                float rs = d_scal[bat];
                int act = sqrtf(rs) > 1e-6f;
                d_scal[12 + bat] = act ? 1.f : 0.f;
                d_scal[4 + bat] = act ? rs / fmaxf(tot, 1e-12f) : 0.f;  // alpha
            }
        }
    }
}

// ------- FUSED data chain stage 1+2: t2 = S_d ⊛ (K ⊛ v), interior only -------
// block (36,8)=288. Output 64x32 tile. t1 lives in smem on a 40x72 region.
__global__ __launch_bounds__(288)
void kc9_k(const float* __restrict__ in, float* __restrict__ out,
           const float* __restrict__ kern, const float* __restrict__ S)
{
    __shared__ float vt[50 * 84];
    __shared__ float t1s[40 * 72];
    __shared__ float sk[121];
    __shared__ float sk9[81];
    const int bc = blockIdx.z;
    const int bat = bc / CC;
    const float* ip = in + (size_t)bc * HWs;
    const int tid = threadIdx.y * 36 + threadIdx.x;
    for (int k = tid; k < 121; k += 288) sk[k] = kern[bat * 121 + k];
    for (int k = tid; k < 81; k += 288) sk9[k] = S[k];
    const int X0 = blockIdx.x * 64, Y0 = blockIdx.y * 32;
    for (int k = tid; k < 50 * 83; k += 288) {
        int sy = k / 83, sx = k % 83;
        int gy = Y0 - 9 + sy, gx = X0 - 9 + sx;
        vt[sy * 84 + sx] = (gy >= 0 && gy < HH && gx >= 0 && gx < WW) ? ip[gy * WW + gx] : 0.f;
    }
    __syncthreads();
    const int tx = threadIdx.x;  // 0..35
    const int ty = threadIdx.y;  // 0..7
    // ---- stage 1: t1 on 40 rows x 72 cols; thread: cols tx, tx+36; rows ty*5..+4 ----
    {
        const int syb = ty * 5;
        float a0[5] = {0, 0, 0, 0, 0}, a1[5] = {0, 0, 0, 0, 0};
#pragma unroll
        for (int a = 0; a < 11; a++) {
            float kc[11];
#pragma unroll
            for (int u = 0; u < 11; u++) kc[u] = sk[u * 11 + a];
#pragma unroll
            for (int rr = 0; rr < 15; rr++) {
                float v0 = vt[(syb + rr) * 84 + tx + a];
                float v1 = vt[(syb + rr) * 84 + tx + 36 + a];
#pragma unroll
                for (int k5 = 0; k5 < 5; k5++) {
                    int u = rr - k5;
                    if (u >= 0 && u <= 10) {
                        a0[k5] += v0 * kc[u];
                        a1[k5] += v1 * kc[u];
                    }
                }
            }
        }
#pragma unroll
        for (int k5 = 0; k5 < 5; k5++) {
            int sy = syb + k5;
            int gy = Y0 - 4 + sy;
            int gx0 = X0 - 4 + tx, gx1 = gx0 + 36;
            bool iy = (gy >= 0 && gy < HH);
            t1s[sy * 72 + tx]      = (iy && gx0 >= 0 && gx0 < WW) ? a0[k5] : 0.f;
            t1s[sy * 72 + tx + 36] = (iy && gx1 < WW)             ? a1[k5] : 0.f;
        }
    }
    __syncthreads();
    if (tx >= 32) return;
    // ---- stage 2: conv9(S_d) over t1s; output cols tx, tx+32; rows ty*4..+3 ----
    const int ry = ty * 4;
    float acc0[4] = {0, 0, 0, 0}, acc1[4] = {0, 0, 0, 0};
#pragma unroll
    for (int a = 0; a < 9; a++) {
        float kc[9];
#pragma unroll
        for (int u = 0; u < 9; u++) kc[u] = sk9[u * 9 + a];
#pragma unroll
        for (int rr = 0; rr < 12; rr++) {
            float v0 = t1s[(ry + rr) * 72 + tx + a];
            float v1 = t1s[(ry + rr) * 72 + tx + 32 + a];
#pragma unroll
            for (int k = 0; k < 4; k++) {
                int u = rr - k;
                if (u >= 0 && u <= 8) {
                    acc0[k] += v0 * kc[u];
                    acc1[k] += v1 * kc[u];
                }
            }
        }
    }
#pragma unroll
    for (int k = 0; k < 4; k++) {
        int oy = Y0 + ry + k;
        if (oy < 2 || oy >= HH - 2) continue;
        size_t rowo = (size_t)bc * HWs + (size_t)oy * WW;
        int ox0 = X0 + tx, ox1 = ox0 + 32;
        if (ox0 >= 2 && ox0 < WW - 2) out[rowo + ox0] = acc0[k];
        if (ox1 >= 2 && ox1 < WW - 2) out[rowo + ox1] = acc1[k];
    }
}

// ------- generic exact two-stage border: out(frame) = sum_i kw_i K_i^T K_i in -------
__global__ __launch_bounds__(256)
void border_k(const float* __restrict__ in, float* __restrict__ out,
              const float* __restrict__ ks, const float* __restrict__ kw, int I)
{
    __shared__ float vsh[6 * 40];
    __shared__ float tsh[4 * 36];
    __shared__ float sk[IRK * 25];
    __shared__ float skw[IRK];
    const int bc = blockIdx.z;
    const int side = blockIdx.x / 12, seg = blockIdx.x % 12;
    const bool horiz = (side < 2);
    const bool farside = (side & 1);
    const int tid = threadIdx.x;
    for (int k = tid; k < I * 25; k += 256) sk[k] = ks[k];
    if (tid < I) skw[tid] = kw[tid];
    const float* ip = in + (size_t)bc * HWs;
    const int lbase = seg * 32;
    if (tid < 240) {
        int i = tid / 40, j = tid % 40;
        int thin = (farside ? 378 : 0) + i;
        int lng = lbase - 4 + j;
        int gy = horiz ? thin : lng;
        int gx = horiz ? lng : thin;
        vsh[tid] = (gy >= 0 && gy < HH && gx >= 0 && gx < WW) ? ip[gy * WW + gx] : 0.f;
    }
    __syncthreads();
    float acc = 0.f;
    for (int i = 0; i < I; i++) {
        __syncthreads();
        if (tid < 144) {
            int it = tid / 36, jt = tid % 36;
            int glong = lbase - 2 + jt;
            float t = 0.f;
            if (glong >= 0 && glong < 384) {
#pragma unroll
                for (int a = 0; a < 5; a++) {
                    int vi = it + a + (farside ? 0 : -2);
                    if (vi >= 0 && vi < 6) {
#pragma unroll
                        for (int b2 = 0; b2 < 5; b2++) {
                            float kv = horiz ? sk[i * 25 + a * 5 + b2] : sk[i * 25 + b2 * 5 + a];
                            t += kv * vsh[vi * 40 + jt + b2];
                        }
                    }
                }
            }
            tsh[tid] = t;
        }
        __syncthreads();
        if (tid < 64) {
            int io = tid / 32, jo = tid % 32;
            float s = 0.f;
#pragma unroll
            for (int a = 0; a < 5; a++) {
                int it = io + (farside ? 4 : 2) - a;
                if (it >= 0 && it < 4) {
#pragma unroll
                    for (int b2 = 0; b2 < 5; b2++) {
                        int jt = jo + 4 - b2;
                        float kv = horiz ? sk[i * 25 + a * 5 + b2] : sk[i * 25 + b2 * 5 + a];
                        s += kv * tsh[it * 36 + jt];
                    }
                }
            }
            acc += skw[i] * s;
        }
    }
    if (tid < 64) {
        int io = tid / 32, jo = tid % 32;
        int thin = (farside ? 382 : 0) + io;
        int lng = lbase + jo;
        int gy = horiz ? thin : lng;
        int gx = horiz ? lng : thin;
        out[(size_t)bc * HWs + (size_t)gy * WW + gx] = acc;
    }
}

// ------- data-term border: computes t1 = K ⊛ v locally, then two-stage on t1 -------
__global__ __launch_bounds__(256)
void borderD_k(const float* __restrict__ v, float* __restrict__ out,
               const float* __restrict__ kern,
               const float* __restrict__ ks, const float* __restrict__ kw)
{
    __shared__ float vsh2[16 * 50];
    __shared__ float t1[6 * 40];
    __shared__ float tsh[4 * 36];
    __shared__ float sk11[121];
    __shared__ float sk[8 * 25];
    __shared__ float skw[8];
    const int bc = blockIdx.z;
    const int bat = bc / CC;
    const int side = blockIdx.x / 12, seg = blockIdx.x % 12;
    const bool horiz = (side < 2);
    const bool farside = (side & 1);
    const int tid = threadIdx.x;
    for (int k = tid; k < 121; k += 256) sk11[k] = kern[bat * 121 + k];
    for (int k = tid; k < 200; k += 256) sk[k] = ks[k];
    if (tid < 8) skw[tid] = kw[tid];
    const float* ip = v + (size_t)bc * HWs;
    const int lbase = seg * 32;
    const int base_t = farside ? 373 : -5;
    for (int k = tid; k < 16 * 50; k += 256) {
        int a = k / 50, b2 = k % 50;
        int thin = base_t + a;
        int lng = lbase - 9 + b2;
        int gy = horiz ? thin : lng;
        int gx = horiz ? lng : thin;
        vsh2[k] = (gy >= 0 && gy < HH && gx >= 0 && gx < WW) ? ip[gy * WW + gx] : 0.f;
    }
    __syncthreads();
    // t1 = K ⊛ v on [6 x 40] strip (zero outside image in the long direction)
    if (tid < 240) {
        int i = tid / 40, j = tid % 40;
        int glong = lbase - 4 + j;
        float t = 0.f;
        if (glong >= 0 && glong < 384) {
#pragma unroll
            for (int u = 0; u < 11; u++) {
#pragma unroll
                for (int vv = 0; vv < 11; vv++) {
                    float kv = horiz ? sk11[u * 11 + vv] : sk11[vv * 11 + u];
                    t += kv * vsh2[(i + u) * 50 + j + vv];
                }
            }
        }
        t1[tid] = t;
    }
    __syncthreads();
    float acc = 0.f;
    for (int i = 0; i < 8; i++) {
        __syncthreads();
        if (tid < 144) {
            int it = tid / 36, jt = tid % 36;
            int glong = lbase - 2 + jt;
            float t = 0.f;
            if (glong >= 0 && glong < 384) {
#pragma unroll
                for (int a = 0; a < 5; a++) {
                    int vi = it + a + (farside ? 0 : -2);
                    if (vi >= 0 && vi < 6) {
#pragma unroll
                        for (int b2 = 0; b2 < 5; b2++) {
                            float kv = horiz ? sk[i * 25 + a * 5 + b2] : sk[i * 25 + b2 * 5 + a];
                            t += kv * t1[vi * 40 + jt + b2];
                        }
                    }
                }
            }
            tsh[tid] = t;
        }
        __syncthreads();
        if (tid < 64) {
            int io = tid / 32, jo = tid % 32;
            float s = 0.f;
#pragma unroll
            for (int a = 0; a < 5; a++) {
                int it = io + (farside ? 4 : 2) - a;
                if (it >= 0 && it < 4) {
#pragma unroll
                    for (int b2 = 0; b2 < 5; b2++) {
                        int jt = jo + 4 - b2;
                        float kv = horiz ? sk[i * 25 + a * 5 + b2] : sk[i * 25 + b2 * 5 + a];
                        s += kv * tsh[it * 36 + jt];
                    }
                }
            }
            acc += skw[i] * s;
        }
    }
    if (tid < 64) {
        int io = tid / 32, jo = tid % 32;
        int thin = (farside ? 382 : 0) + io;
        int lng = lbase + jo;
        int gy = horiz ? thin : lng;
        int gx = horiz ? lng : thin;
        out[(size_t)bc * HWs + (size_t)gy * WW + gx] = acc;
    }
}

// ------- 9x9 composed conv, interior only. 64x32 tile, block (32,8) -------
__global__ __launch_bounds__(256)
void conv9_k(const float* __restrict__ in, float* __restrict__ out,
             const float* __restrict__ S)
{
    __shared__ float tile[40 * 72];
    __shared__ float sk[81];
    const int bc = blockIdx.z;
    const float* ip = in + (size_t)bc * HWs;
    const int tid = threadIdx.y * 32 + threadIdx.x;
    if (tid < 81) sk[tid] = S[tid];
    const int X0 = blockIdx.x * 64, Y0 = blockIdx.y * 32;
    for (int k = tid; k < 40 * 72; k += 256) {
        int sy = k / 72, sx = k % 72;
        int gy = Y0 - 4 + sy, gx = X0 - 4 + sx;
        tile[k] = (gy >= 0 && gy < HH && gx >= 0 && gx < WW) ? ip[gy * WW + gx] : 0.f;
    }
    __syncthreads();
    const int ry = threadIdx.y * 4;
    const int tx = threadIdx.x;
    float acc0[4] = {0, 0, 0, 0}, acc1[4] = {0, 0, 0, 0};
#pragma unroll
    for (int a = 0; a < 9; a++) {
        float kc[9];
#pragma unroll
        for (int u = 0; u < 9; u++) kc[u] = sk[u * 9 + a];
#pragma unroll
        for (int rr = 0; rr < 12; rr++) {
            float v0 = tile[(ry + rr) * 72 + tx + a];
            float v1 = tile[(ry + rr) * 72 + tx + 32 + a];
#pragma unroll
            for (int k = 0; k < 4; k++) {
                int u = rr - k;
                if (u >= 0 && u <= 8) {
                    acc0[k] += v0 * kc[u];
                    acc1[k] += v1 * kc[u];
                }
            }
        }
    }
#pragma unroll
    for (int k = 0; k < 4; k++) {
        int oy = Y0 + ry + k;
        if (oy < 2 || oy >= HH - 2) continue;
        size_t rowo = (size_t)bc * HWs + (size_t)oy * WW;
        int ox0 = X0 + tx, ox1 = ox0 + 32;
        if (ox0 >= 2 && ox0 < WW - 2) out[rowo + ox0] = acc0[k];
        if (ox1 >= 2 && ox1 < WW - 2) out[rowo + ox1] = acc1[k];
    }
}

// -------- fused out = sum_i K_i^T ( kw_i * wreg_i * (K_i v) ), iter-1 reg term --------
__global__ __launch_bounds__(288)
void ata_k(const float* __restrict__ in, float* __restrict__ out,
           const float* __restrict__ ks, const float* __restrict__ kw,
           const float* __restrict__ wreg)
{
    __shared__ float vt[40 * 40];
    __shared__ float tt[2][36 * 36];
    __shared__ float sk[IRK * 25];
    __shared__ float skw[IRK];
    const int bc = blockIdx.z;
    const float* ip = in + (size_t)bc * HWs;
    const int tid = threadIdx.y * 36 + threadIdx.x;
    for (int k = tid; k < IRK * 25; k += 288) sk[k] = ks[k];
    if (tid < IRK) skw[tid] = kw[tid];
    const int X0 = blockIdx.x * 32, Y0 = blockIdx.y * 32;
    for (int k = tid; k < 40 * 40; k += 288) {
        int sy = k / 40, sx = k % 40;
        int gy = Y0 - 4 + sy, gx = X0 - 4 + sx;
        vt[k] = (gy >= 0 && gy < HH && gx >= 0 && gx < WW) ? ip[gy * WW + gx] : 0.f;
    }
    __syncthreads();
    const int tx = threadIdx.x;
    const int ty = threadIdx.y;
    const int syb = ty * 5;
    float a0 = 0, a1 = 0, a2 = 0, a3 = 0;
    int buf = 0;
    for (int i = 0; i < IRK; i++) {
        float kr[25];
#pragma unroll
        for (int k = 0; k < 25; k++) kr[k] = sk[i * 25 + k];
        const float kwv = skw[i];
        float tv0 = 0, tv1 = 0, tv2 = 0, tv3 = 0, tv4 = 0;
#pragma unroll
        for (int v = 0; v < 5; v++) {
#pragma unroll
            for (int rr = 0; rr < 9; rr++) {
                float val = vt[(syb + rr) * 40 + tx + v];
                int u;
                u = rr;     if (u <= 4)            tv0 += val * kr[u * 5 + v];
                u = rr - 1; if (u >= 0 && u <= 4)  tv1 += val * kr[u * 5 + v];
                u = rr - 2; if (u >= 0 && u <= 4)  tv2 += val * kr[u * 5 + v];
                u = rr - 3; if (u >= 0 && u <= 4)  tv3 += val * kr[u * 5 + v];
                u = rr - 4; if (u >= 0)            tv4 += val * kr[u * 5 + v];
            }
        }
        {
            float tvs[5] = {tv0, tv1, tv2, tv3, tv4};
#pragma unroll
            for (int k = 0; k < 5; k++) {
                int sy = syb + k;
                if (sy < 36) {
                    int gy = Y0 - 2 + sy, gx = X0 - 2 + tx;
                    float o = 0.f;
                    if (gy >= 0 && gy < HH && gx >= 0 && gx < WW) {
                        float w = kwv * wreg[((size_t)(bc * IRK + i)) * HWs + (size_t)gy * WW + gx];
                        o = tvs[k] * w;
                    }
                    tt[buf][sy * 36 + tx] = o;
                }
            }
        }
        __syncthreads();
        if (tx < 32) {
            const int ry = ty * 4;
#pragma unroll
            for (int v = 0; v < 5; v++) {
                int col = tx + 4 - v;
#pragma unroll
                for (int rr = 0; rr < 8; rr++) {
                    float val = tt[buf][(ry + rr) * 36 + col];
                    int u;
                    u = 4 - rr; if (u >= 0 && u <= 4) a0 += val * kr[u * 5 + v];
                    u = 5 - rr; if (u >= 0 && u <= 4) a1 += val * kr[u * 5 + v];
                    u = 6 - rr; if (u >= 0 && u <= 4) a2 += val * kr[u * 5 + v];
                    u = 7 - rr; if (u >= 0 && u <= 4) a3 += val * kr[u * 5 + v];
                }
            }
        }
        buf ^= 1;
    }
    if (tx < 32) {
        const int ry = ty * 4;
        float accs[4] = {a0, a1, a2, a3};
#pragma unroll
        for (int k2 = 0; k2 < 4; k2++) {
            size_t o = (size_t)bc * HWs + (size_t)(Y0 + ry + k2) * WW + X0 + tx;
            out[o] = accs[k2];
        }
    }
}

// -------- GMM reweighting --------
__global__ __launch_bounds__(256)
void gmm_k(const float* __restrict__ x, const float* __restrict__ rks,
           const float* __restrict__ gw, const float* __restrict__ giv)
{
    __shared__ float tile[36 * 36];
    __shared__ float sk[IRK * 25];
    const int bc = blockIdx.z;
    const float* ip = x + (size_t)bc * HWs;
    const int tid = threadIdx.y * 32 + threadIdx.x;
    for (int k = tid; k < IRK * 25; k += 256) sk[k] = rks[k];
    const int X0 = blockIdx.x * 32, Y0 = blockIdx.y * 32;
    for (int k = tid; k < 36 * 36; k += 256) {
        int sy = k / 36, sx = k % 36;
        int gy = Y0 - 2 + sy, gx = X0 - 2 + sx;
        tile[k] = (gy >= 0 && gy < HH && gx >= 0 && gx < WW) ? ip[gy * WW + gx] : 0.f;
    }
    __syncthreads();
    const int ry = threadIdx.y * 4, tx = threadIdx.x;
    for (int j = 0; j < IRK; j++) {
        float kr[25];
#pragma unroll
        for (int k = 0; k < 25; k++) kr[k] = sk[j * 25 + k];
        float g0 = 0, g1 = 0, g2 = 0, g3 = 0;
#pragma unroll
        for (int v = 0; v < 5; v++) {
#pragma unroll
            for (int rr = 0; rr < 8; rr++) {
                float val = tile[(ry + rr) * 36 + tx + v];
                int u;
                u = rr;     if (u <= 4)           g0 += val * kr[u * 5 + v];
                u = rr - 1; if (u >= 0 && u <= 4) g1 += val * kr[u * 5 + v];
                u = rr - 2; if (u >= 0 && u <= 4) g2 += val * kr[u * 5 + v];
                u = rr - 3; if (u >= 0)           g3 += val * kr[u * 5 + v];
            }
        }
        float iv0 = giv[0 * IRK + j], iv1 = giv[1 * IRK + j], iv2 = giv[2 * IRK + j];
        float c0 = gw[0 * IRK + j] * sqrtf(iv0);
        float c1 = gw[1 * IRK + j] * sqrtf(iv1);
        float c2 = gw[2 * IRK + j] * sqrtf(iv2);
        float gs[4] = {g0, g1, g2, g3};
#pragma unroll
        for (int k2 = 0; k2 < 4; k2++) {
            float gv = gs[k2];
            float p0 = c0 * expf(-0.5f * iv0 * gv * gv);
            float p1 = c1 * expf(-0.5f * iv1 * gv * gv);
            float p2 = c2 * expf(-0.5f * iv2 * gv * gv);
            float num = p0 * iv0 + p1 * iv1 + p2 * iv2;
            float den = p0 + p1 + p2 + 1e-12f;
            d_wreg[((size_t)(bc * IRK + j)) * HWs + (size_t)(Y0 + ry + k2) * WW + X0 + tx] = num / den;
        }
    }
}

// ------- fused CG update: x+=αp, r-=αAp, rs/beta, then (spin) p=r+βp -------
// grid (108, BB). All 432 blocks co-resident (minblocks 3 guarantees ≥444 slots).
__global__ void __launch_bounds__(256, 3)
update2_k(float* __restrict__ x, int do_p)
{
    const int b = blockIdx.y;
    const float alpha = d_scal[4 + b];
    float4* x4 = (float4*)x;
    float4* p4 = (float4*)d_p;
    float4* r4 = (float4*)d_r;
    float4* a4 = (float4*)d_Ap;
    size_t base = (size_t)b * (NBE / 4) + (size_t)blockIdx.x * 1024 + threadIdx.x;
    float4 pv[4], rv[4];
    float s = 0.f;
#pragma unroll
    for (int k = 0; k < 4; k++) {
        size_t i4 = base + (size_t)k * 256;
        float4 xv = x4[i4];
        pv[k] = p4[i4]; rv[k] = r4[i4];
        float4 av = a4[i4];
        xv.x += alpha * pv[k].x; xv.y += alpha * pv[k].y;
        xv.z += alpha * pv[k].z; xv.w += alpha * pv[k].w;
        rv[k].x -= alpha * av.x; rv[k].y -= alpha * av.y;
        rv[k].z -= alpha * av.z; rv[k].w -= alpha * av.w;
        x4[i4] = xv; r4[i4] = rv[k];
        s += rv[k].x * rv[k].x + rv[k].y * rv[k].y
           + rv[k].z * rv[k].z + rv[k].w * rv[k].w;
    }
    float tot;
    bool last = lastBlockTotal(threadIdx.x, s, b, blockIdx.x, NP_UPD, &tot);
    if (last && threadIdx.x == 0) {
        float rs = d_scal[b];
        int act = d_scal[12 + b] != 0.f;
        d_scal[8 + b] = act ? tot / fmaxf(rs, 1e-12f) : 0.f;  // beta
        d_scal[b] = act ? tot : rs;                            // rs
        __threadfence();
        if (do_p) d_flag[b] = 1;
    }
    if (!do_p) return;
    if (threadIdx.x == 0) {
        while (d_flag[b] == 0) { }
    }
    __syncthreads();
    __threadfence();
    const float beta = d_scal[8 + b];
    const int act = d_scal[12 + b] != 0.f;
    if (act) {
#pragma unroll
        for (int k = 0; k < 4; k++) {
            size_t i4 = base + (size_t)k * 256;
            float4 pn;
            pn.x = rv[k].x + beta * pv[k].x; pn.y = rv[k].y + beta * pv[k].y;
            pn.z = rv[k].z + beta * pv[k].z; pn.w = rv[k].w + beta * pv[k].w;
            p4[i4] = pn;
        }
    }
    __threadfence();
    __syncthreads();
    if (threadIdx.x == 0) {
        int old = atomicAdd(&d_cnt[4 + b], 1);
        if (old == NP_UPD - 1) { d_cnt[4 + b] = 0; d_flag[b] = 0; }
    }
}

// ---------------- host orchestration ----------------
struct Ptrs {
    float *b, *Ap, *t1, *t2, *wreg, *p, *S;
};

extern "C" void kernel_launch(void* const* d_in, const int* in_sizes, int n_in,
                              void* d_out, int out_size)
{
    const float* blurred = (const float*)d_in[0];
    const float* kern    = (const float*)d_in[1];
    const float* dkw     = (const float*)d_in[2];
    const float* dks     = (const float*)d_in[3];
    const float* rkw     = (const float*)d_in[4];
    const float* rks     = (const float*)d_in[5];
    const float* gmmw    = (const float*)d_in[6];
    const float* gmmiv   = (const float*)d_in[7];
    float* x = (float*)d_out;

    Ptrs P;
    cudaGetSymbolAddress((void**)&P.b, d_b);
    cudaGetSymbolAddress((void**)&P.Ap, d_Ap);
    cudaGetSymbolAddress((void**)&P.t1, d_t1);
    cudaGetSymbolAddress((void**)&P.t2, d_t2);
    cudaGetSymbolAddress((void**)&P.wreg, d_wreg);
    cudaGetSymbolAddress((void**)&P.p, d_p);
    cudaGetSymbolAddress((void**)&P.S, d_S);
    void* pcnt;
    cudaGetSymbolAddress(&pcnt, d_cnt);

    const int n_irls = 2, n_cg = 8;
    dim3 gc(6, 12, NBC), bl(32, 8);
    dim3 gk(6, 12, NBC), bk(36, 8);
    dim3 gb(48, 1, NBC);
    dim3 ga(12, 12, NBC), ba(36, 8);
    dim3 gu(NP_UPD, BB);

    cudaStream_t s1;
    cudaStreamCreateWithFlags(&s1, cudaStreamNonBlocking);
    cudaEvent_t e0, eB;
    cudaEventCreateWithFlags(&e0, cudaEventDisableTiming);
    cudaEventCreateWithFlags(&eB, cudaEventDisableTiming);

    cudaMemsetAsync(pcnt, 0, 8 * sizeof(int), 0);
    autocorr_k<<<1, 256, 0, 0>>>(dks, dkw, rks, rkw);

    // fork: x = blurred on side stream; b-precompute on main
    cudaEventRecord(e0, 0);
    cudaStreamWaitEvent(s1, e0, 0);
    cudaMemcpyAsync(x, blurred, (size_t)NTOT * sizeof(float),
                    cudaMemcpyDeviceToDevice, s1);
    conv9_k<<<gc, bl, 0, 0>>>(blurred, P.t1, P.S);
    border_k<<<gb, 256, 0, 0>>>(blurred, P.t1, dks, dkw, 8);
    corr11_k<<<gc, bl, 0, 0>>>(P.t1, P.b, kern, 1, 0, nullptr);
    cudaEventRecord(eB, s1);
    cudaStreamWaitEvent(0, eB, 0);

    // Aop: side stream runs the reg term (and gmm when requested); main runs
    // the fused data chain. mode_final: 1=fused dot+alpha, 2=fused resid+rs.
    auto AopL = [&](const float* v, int iter, int mode_final, const float* dv,
                    bool pre_gmm) {
        cudaEventRecord(e0, 0);
        cudaStreamWaitEvent(s1, e0, 0);
        if (pre_gmm)
            gmm_k<<<dim3(12, 12, NBC), dim3(32, 8), 0, s1>>>(x, rks, gmmw, gmmiv);
        if (iter == 0) {
            conv9_k<<<gc, bl, 0, s1>>>(v, P.Ap, P.S + 81);
            border_k<<<gb, 256, 0, s1>>>(v, P.Ap, rks, rkw, IRK);
        } else {
            ata_k<<<ga, ba, 0, s1>>>(v, P.Ap, rks, rkw, P.wreg);
        }
        cudaEventRecord(eB, s1);
        // main: fused data chain; borderD computes its own t1 from v
        kc9_k<<<gk, bk, 0, 0>>>(v, P.t2, kern, P.S);
        borderD_k<<<gb, 256, 0, 0>>>(v, P.t2, kern, dks, dkw);
        cudaStreamWaitEvent(0, eB, 0);
        corr11_k<<<gc, bl, 0, 0>>>(P.t2, P.Ap, kern, 1, mode_final, dv);
    };

    for (int it = 0; it < n_irls; it++) {
        AopL(x, it, 2, nullptr, it == 1);
        for (int s = 0; s < n_cg; s++) {
            AopL(P.p, it, 1, P.p, false);
            update2_k<<<gu, 256, 0, 0>>>(x, s < n_cg - 1 ? 1 : 0);
        }
    }

    cudaEventDestroy(e0);
    cudaEventDestroy(eB);
    cudaStreamDestroy(s1);
}

// round 11
// speedup vs baseline: 1.0529x; 1.0529x over previous
#include <cuda_runtime.h>
#include <math.h>

#define BB 4
#define CC 3
#define HH 384
#define WW 384
#define HWs (HH*WW)
#define NBC 12
#define NTOT (NBC*HWs)
#define NBE (CC*HWs)
#define IRK 16
#define NP_CORR 216   // corr11 blocks per batch (6*12*3)
#define NP_UPD  108   // update2 blocks per batch

// ------------ static device scratch ------------
__device__ float d_b[NTOT];
__device__ float d_r[NTOT];
__device__ float d_p[NTOT];
__device__ float d_Ap[NTOT];
__device__ float d_t1[NTOT];
__device__ float d_t2[NTOT];
__device__ float d_wreg[(size_t)IRK * NTOT];
__device__ float d_part[BB * 512];
__device__ float d_scal[16]; // [0..3]=rs [4..7]=alpha [8..11]=beta [12..15]=active
__device__ float d_S[162];   // [0..80]=S_data  [81..161]=S_reg
__device__ int   d_cnt[8];   // completion counters (self-resetting)
__device__ volatile int d_flag[4];

__device__ __forceinline__ float warpRed(float v) {
#pragma unroll
    for (int o = 16; o > 0; o >>= 1) v += __shfl_down_sync(0xffffffffu, v, o);
    return v;
}

// Block-reduce s, store partial, detect last block of batch b, then cooperatively
// reduce all nblk partials. Returns true on ALL threads of the last block.
__device__ __forceinline__ bool lastBlockTotal(int tid, float s, int b, int slot,
                                               int nblk, float* tot) {
    __shared__ float sm[8];
    __shared__ int lastF;
    float w = warpRed(s);
    if ((tid & 31) == 0) sm[tid >> 5] = w;
    __syncthreads();
    if (tid == 0) {
        float v = 0;
#pragma unroll
        for (int i = 0; i < 8; i++) v += sm[i];
        d_part[b * 512 + slot] = v;
        __threadfence();
        int old = atomicAdd(&d_cnt[b], 1);
        lastF = (old == nblk - 1);
        if (lastF) d_cnt[b] = 0;
    }
    __syncthreads();
    if (!lastF) return false;
    float t = 0;
    for (int i = tid; i < nblk; i += 256) t += d_part[b * 512 + i];
    t = warpRed(t);
    __syncthreads();
    if ((tid & 31) == 0) sm[tid >> 5] = t;
    __syncthreads();
    float v = 0;
#pragma unroll
    for (int i = 0; i < 8; i++) v += sm[i];
    *tot = v;
    return true;
}

// ------- build composed 9x9 kernels S(d) = sum_i kw_i sum_e k_i(e) k_i(e+d) -------
__global__ void autocorr_k(const float* __restrict__ dks, const float* __restrict__ dkw,
                           const float* __restrict__ rks, const float* __restrict__ rkw)
{
    int tid = threadIdx.x;
    if (tid < 162) {
        int which = tid / 81, t = tid % 81;
        const float* ks = which ? rks : dks;
        const float* kw = which ? rkw : dkw;
        int I = which ? 16 : 8;
        int dy = t / 9 - 4, dx = t % 9 - 4;
        float s = 0.f;
        for (int i = 0; i < I; i++) {
            float w = kw[i];
            for (int u = 0; u < 5; u++)
                for (int v = 0; v < 5; v++) {
                    int u2 = u + dy, v2 = v + dx;
                    if (u2 >= 0 && u2 < 5 && v2 >= 0 && v2 < 5)
                        s += w * ks[i * 25 + u * 5 + v] * ks[i * 25 + u2 * 5 + v2];
                }
        }
        d_S[which * 81 + t] = s;
    }
}

// ---------------- 11x11 per-batch correlation, SAME, zero pad ----------------
// 64x32 tile, block (32,8). thread tx covers cols tx and tx+32.
// mode 0: out = acc
// mode 1: out += acc; fused dot(out_new, dv); last block computes alpha/active
// mode 2: Ap = out+acc; rv=b-Ap; r=p=rv; fused rs; last block stores rs
__global__ __launch_bounds__(256)
void corr11_k(const float* __restrict__ in, float* __restrict__ out,
              const float* __restrict__ kern, int flip, int mode,
              const float* __restrict__ dv)
{
    __shared__ float tile[42 * 74];
    __shared__ float sk[121];
    const int bc = blockIdx.z;
    const int bat = bc / CC;
    const float* ip = in + (size_t)bc * HWs;
    const int tid = threadIdx.y * 32 + threadIdx.x;
    if (tid < 121) sk[tid] = kern[bat * 121 + (flip ? 120 - tid : tid)];
    const int X0 = blockIdx.x * 64, Y0 = blockIdx.y * 32;
    for (int k = tid; k < 42 * 74; k += 256) {
        int sy = k / 74, sx = k % 74;
        int gy = Y0 - 5 + sy, gx = X0 - 5 + sx;
        tile[k] = (gy >= 0 && gy < HH && gx >= 0 && gx < WW) ? ip[gy * WW + gx] : 0.f;
    }
    __syncthreads();
    const int ry = threadIdx.y * 4;
    const int tx = threadIdx.x;
    float acc0[4] = {0, 0, 0, 0}, acc1[4] = {0, 0, 0, 0};
#pragma unroll
    for (int a = 0; a < 11; a++) {
        float kc[11];
#pragma unroll
        for (int u = 0; u < 11; u++) kc[u] = sk[u * 11 + a];
#pragma unroll
        for (int rr = 0; rr < 14; rr++) {
            float v0 = tile[(ry + rr) * 74 + tx + a];
            float v1 = tile[(ry + rr) * 74 + tx + 32 + a];
#pragma unroll
            for (int k = 0; k < 4; k++) {
                int u = rr - k;
                if (u >= 0 && u <= 10) {
                    acc0[k] += v0 * kc[u];
                    acc1[k] += v1 * kc[u];
                }
            }
        }
    }
    size_t obase = (size_t)bc * HWs + (size_t)(Y0 + ry) * WW + X0 + tx;
    if (mode == 0) {
#pragma unroll
        for (int k = 0; k < 4; k++) {
            out[obase + (size_t)k * WW] = acc0[k];
            out[obase + (size_t)k * WW + 32] = acc1[k];
        }
        return;
    }
    float s = 0.f;
    if (mode == 1) {
#pragma unroll
        for (int k = 0; k < 4; k++) {
            size_t o = obase + (size_t)k * WW;
            float a0 = out[o] + acc0[k]; out[o] = a0; s += a0 * dv[o];
            size_t o1 = o + 32;
            float a1 = out[o1] + acc1[k]; out[o1] = a1; s += a1 * dv[o1];
        }
    } else {
#pragma unroll
        for (int k = 0; k < 4; k++) {
            size_t o = obase + (size_t)k * WW;
            float a0 = out[o] + acc0[k];
            float rv0 = d_b[o] - a0; d_r[o] = rv0; d_p[o] = rv0; s += rv0 * rv0;
            size_t o1 = o + 32;
            float a1 = out[o1] + acc1[k];
            float rv1 = d_b[o1] - a1; d_r[o1] = rv1; d_p[o1] = rv1; s += rv1 * rv1;
        }
    }
    int slot = (bc % CC) * 72 + blockIdx.y * 6 + blockIdx.x;
    float tot;
    if (lastBlockTotal(tid, s, bat, slot, NP_CORR, &tot)) {
        if (tid == 0) {
            if (mode == 2) {
                d_scal[bat] = tot;                 // rs
            } else {
                float rs = d_scal[bat];
                int act = sqrtf(rs) > 1e-6f;
                d_scal[12 + bat] = act ? 1.f : 0.f;
                d_scal[4 + bat] = act ? rs / fmaxf(tot, 1e-12f) : 0.f;  // alpha
            }
        }
    }
}

// ------- 9x9 composed conv, interior only. 64x32 tile, block (32,8) -------
__global__ __launch_bounds__(256)
void conv9_k(const float* __restrict__ in, float* __restrict__ out,
             const float* __restrict__ S)
{
    __shared__ float tile[40 * 72];
    __shared__ float sk[81];
    const int bc = blockIdx.z;
    const float* ip = in + (size_t)bc * HWs;
    const int tid = threadIdx.y * 32 + threadIdx.x;
    if (tid < 81) sk[tid] = S[tid];
    const int X0 = blockIdx.x * 64, Y0 = blockIdx.y * 32;
    for (int k = tid; k < 40 * 72; k += 256) {
        int sy = k / 72, sx = k % 72;
        int gy = Y0 - 4 + sy, gx = X0 - 4 + sx;
        tile[k] = (gy >= 0 && gy < HH && gx >= 0 && gx < WW) ? ip[gy * WW + gx] : 0.f;
    }
    __syncthreads();
    const int ry = threadIdx.y * 4;
    const int tx = threadIdx.x;
    float acc0[4] = {0, 0, 0, 0}, acc1[4] = {0, 0, 0, 0};
#pragma unroll
    for (int a = 0; a < 9; a++) {
        float kc[9];
#pragma unroll
        for (int u = 0; u < 9; u++) kc[u] = sk[u * 9 + a];
#pragma unroll
        for (int rr = 0; rr < 12; rr++) {
            float v0 = tile[(ry + rr) * 72 + tx + a];
            float v1 = tile[(ry + rr) * 72 + tx + 32 + a];
#pragma unroll
            for (int k = 0; k < 4; k++) {
                int u = rr - k;
                if (u >= 0 && u <= 8) {
                    acc0[k] += v0 * kc[u];
                    acc1[k] += v1 * kc[u];
                }
            }
        }
    }
#pragma unroll
    for (int k = 0; k < 4; k++) {
        int oy = Y0 + ry + k;
        if (oy < 2 || oy >= HH - 2) continue;
        size_t rowo = (size_t)bc * HWs + (size_t)oy * WW;
        int ox0 = X0 + tx, ox1 = ox0 + 32;
        if (ox0 >= 2 && ox0 < WW - 2) out[rowo + ox0] = acc0[k];
        if (ox1 >= 2 && ox1 < WW - 2) out[rowo + ox1] = acc1[k];
    }
}

// ------- exact two-stage sum_i kw_i K_i^T K_i on the 2-pixel border frame -------
__global__ __launch_bounds__(256)
void border_k(const float* __restrict__ in, float* __restrict__ out,
              const float* __restrict__ ks, const float* __restrict__ kw, int I)
{
    __shared__ float vsh[6 * 40];
    __shared__ float tsh[4 * 36];
    __shared__ float sk[IRK * 25];
    __shared__ float skw[IRK];
    const int bc = blockIdx.z;
    const int side = blockIdx.x / 12, seg = blockIdx.x % 12;
    const bool horiz = (side < 2);
    const bool farside = (side & 1);
    const int tid = threadIdx.x;
    for (int k = tid; k < I * 25; k += 256) sk[k] = ks[k];
    if (tid < I) skw[tid] = kw[tid];
    const float* ip = in + (size_t)bc * HWs;
    const int lbase = seg * 32;
    if (tid < 240) {
        int i = tid / 40, j = tid % 40;
        int thin = (farside ? 378 : 0) + i;
        int lng = lbase - 4 + j;
        int gy = horiz ? thin : lng;
        int gx = horiz ? lng : thin;
        vsh[tid] = (gy >= 0 && gy < HH && gx >= 0 && gx < WW) ? ip[gy * WW + gx] : 0.f;
    }
    __syncthreads();
    float acc = 0.f;
    for (int i = 0; i < I; i++) {
        __syncthreads();
        if (tid < 144) {
            int it = tid / 36, jt = tid % 36;
            int glong = lbase - 2 + jt;
            float t = 0.f;
            if (glong >= 0 && glong < 384) {
#pragma unroll
                for (int a = 0; a < 5; a++) {
                    int vi = it + a + (farside ? 0 : -2);
                    if (vi >= 0 && vi < 6) {
#pragma unroll
                        for (int b2 = 0; b2 < 5; b2++) {
                            float kv = horiz ? sk[i * 25 + a * 5 + b2] : sk[i * 25 + b2 * 5 + a];
                            t += kv * vsh[vi * 40 + jt + b2];
                        }
                    }
                }
            }
            tsh[tid] = t;
        }
        __syncthreads();
        if (tid < 64) {
            int io = tid / 32, jo = tid % 32;
            float s = 0.f;
#pragma unroll
            for (int a = 0; a < 5; a++) {
                int it = io + (farside ? 4 : 2) - a;
                if (it >= 0 && it < 4) {
#pragma unroll
                    for (int b2 = 0; b2 < 5; b2++) {
                        int jt = jo + 4 - b2;
                        float kv = horiz ? sk[i * 25 + a * 5 + b2] : sk[i * 25 + b2 * 5 + a];
                        s += kv * tsh[it * 36 + jt];
                    }
                }
            }
            acc += skw[i] * s;
        }
    }
    if (tid < 64) {
        int io = tid / 32, jo = tid % 32;
        int thin = (farside ? 382 : 0) + io;
        int lng = lbase + jo;
        int gy = horiz ? thin : lng;
        int gx = horiz ? lng : thin;
        out[(size_t)bc * HWs + (size_t)gy * WW + gx] = acc;
    }
}

// -------- fused out = sum_i K_i^T ( kw_i * wreg_i * (K_i v) ), iter-1 reg term --------
// 64x32 output tile, block (32,8). t_i double-buffered in smem (36x68 region).
__global__ __launch_bounds__(256)
void ata_k(const float* __restrict__ in, float* __restrict__ out,
           const float* __restrict__ ks, const float* __restrict__ kw,
           const float* __restrict__ wreg)
{
    __shared__ float vt[40 * 72];
    __shared__ float tt[2][36 * 68];
    __shared__ float sk[IRK * 25];
    __shared__ float skw[IRK];
    const int bc = blockIdx.z;
    const float* ip = in + (size_t)bc * HWs;
    const int tid = threadIdx.y * 32 + threadIdx.x;
    for (int k = tid; k < IRK * 25; k += 256) sk[k] = ks[k];
    if (tid < IRK) skw[tid] = kw[tid];
    const int X0 = blockIdx.x * 64, Y0 = blockIdx.y * 32;
    for (int k = tid; k < 40 * 72; k += 256) {
        int sy = k / 72, sx = k % 72;
        int gy = Y0 - 4 + sy, gx = X0 - 4 + sx;
        vt[k] = (gy >= 0 && gy < HH && gx >= 0 && gx < WW) ? ip[gy * WW + gx] : 0.f;
    }
    __syncthreads();
    const int tx = threadIdx.x;
    const int ty = threadIdx.y;
    const int ry = ty * 4;
    float acc0[4] = {0, 0, 0, 0}, acc1[4] = {0, 0, 0, 0};
    int buf = 0;
    for (int i = 0; i < IRK; i++) {
        float kr[25];
#pragma unroll
        for (int k = 0; k < 25; k++) kr[k] = sk[i * 25 + k];
        const float kwv = skw[i];
        // ---- stage 1: weighted t_i over the 36x68 halo region ----
        for (int idx = tid; idx < 36 * 68; idx += 256) {
            int sy = idx / 68, sx = idx % 68;
            int gy = Y0 - 2 + sy, gx = X0 - 2 + sx;
            float o = 0.f;
            if (gy >= 0 && gy < HH && gx >= 0 && gx < WW) {
                float t = 0.f;
#pragma unroll
                for (int u = 0; u < 5; u++)
#pragma unroll
                    for (int v = 0; v < 5; v++)
                        t += kr[u * 5 + v] * vt[(sy + u) * 72 + sx + v];
                o = t * kwv * wreg[((size_t)(bc * IRK + i)) * HWs + (size_t)gy * WW + gx];
            }
            tt[buf][idx] = o;
        }
        __syncthreads();
        // ---- stage 2: adjoint into per-thread accumulators ----
#pragma unroll
        for (int v = 0; v < 5; v++) {
            int c0 = tx + 4 - v;
#pragma unroll
            for (int rr = 0; rr < 8; rr++) {
                float v0 = tt[buf][(ry + rr) * 68 + c0];
                float v1 = tt[buf][(ry + rr) * 68 + c0 + 32];
#pragma unroll
                for (int k = 0; k < 4; k++) {
                    int u = k + 4 - rr;
                    if (u >= 0 && u <= 4) {
                        acc0[k] += v0 * kr[u * 5 + v];
                        acc1[k] += v1 * kr[u * 5 + v];
                    }
                }
            }
        }
        buf ^= 1;
    }
#pragma unroll
    for (int k = 0; k < 4; k++) {
        size_t o = (size_t)bc * HWs + (size_t)(Y0 + ry + k) * WW + X0 + tx;
        out[o] = acc0[k];
        out[o + 32] = acc1[k];
    }
}

// -------- GMM reweighting --------
__global__ __launch_bounds__(256)
void gmm_k(const float* __restrict__ x, const float* __restrict__ rks,
           const float* __restrict__ gw, const float* __restrict__ giv)
{
    __shared__ float tile[36 * 36];
    __shared__ float sk[IRK * 25];
    const int bc = blockIdx.z;
    const float* ip = x + (size_t)bc * HWs;
    const int tid = threadIdx.y * 32 + threadIdx.x;
    for (int k = tid; k < IRK * 25; k += 256) sk[k] = rks[k];
    const int X0 = blockIdx.x * 32, Y0 = blockIdx.y * 32;
    for (int k = tid; k < 36 * 36; k += 256) {
        int sy = k / 36, sx = k % 36;
        int gy = Y0 - 2 + sy, gx = X0 - 2 + sx;
        tile[k] = (gy >= 0 && gy < HH && gx >= 0 && gx < WW) ? ip[gy * WW + gx] : 0.f;
    }
    __syncthreads();
    const int ry = threadIdx.y * 4, tx = threadIdx.x;
    for (int j = 0; j < IRK; j++) {
        float kr[25];
#pragma unroll
        for (int k = 0; k < 25; k++) kr[k] = sk[j * 25 + k];
        float g0 = 0, g1 = 0, g2 = 0, g3 = 0;
#pragma unroll
        for (int v = 0; v < 5; v++) {
#pragma unroll
            for (int rr = 0; rr < 8; rr++) {
                float val = tile[(ry + rr) * 36 + tx + v];
                int u;
                u = rr;     if (u <= 4)           g0 += val * kr[u * 5 + v];
                u = rr - 1; if (u >= 0 && u <= 4) g1 += val * kr[u * 5 + v];
                u = rr - 2; if (u >= 0 && u <= 4) g2 += val * kr[u * 5 + v];
                u = rr - 3; if (u >= 0)           g3 += val * kr[u * 5 + v];
            }
        }
        float iv0 = giv[0 * IRK + j], iv1 = giv[1 * IRK + j], iv2 = giv[2 * IRK + j];
        float c0 = gw[0 * IRK + j] * sqrtf(iv0);
        float c1 = gw[1 * IRK + j] * sqrtf(iv1);
        float c2 = gw[2 * IRK + j] * sqrtf(iv2);
        float gs[4] = {g0, g1, g2, g3};
#pragma unroll
        for (int k2 = 0; k2 < 4; k2++) {
            float gv = gs[k2];
            float p0 = c0 * expf(-0.5f * iv0 * gv * gv);
            float p1 = c1 * expf(-0.5f * iv1 * gv * gv);
            float p2 = c2 * expf(-0.5f * iv2 * gv * gv);
            float num = p0 * iv0 + p1 * iv1 + p2 * iv2;
            float den = p0 + p1 + p2 + 1e-12f;
            d_wreg[((size_t)(bc * IRK + j)) * HWs + (size_t)(Y0 + ry + k2) * WW + X0 + tx] = num / den;
        }
    }
}

// ------- fused CG update: x+=αp, r-=αAp, rs/beta, then (spin) p=r+βp -------
// grid (108, BB) = 432 blocks, all co-resident (256 thr/block, 8 blocks/SM cap).
__global__ void __launch_bounds__(256, 3)
update2_k(float* __restrict__ x, int do_p)
{
    const int b = blockIdx.y;
    const float alpha = d_scal[4 + b];
    float4* x4 = (float4*)x;
    float4* p4 = (float4*)d_p;
    float4* r4 = (float4*)d_r;
    float4* a4 = (float4*)d_Ap;
    size_t base = (size_t)b * (NBE / 4) + (size_t)blockIdx.x * 1024 + threadIdx.x;
    float4 pv[4], rv[4];
    float s = 0.f;
#pragma unroll
    for (int k = 0; k < 4; k++) {
        size_t i4 = base + (size_t)k * 256;
        float4 xv = x4[i4];
        pv[k] = p4[i4]; rv[k] = r4[i4];
        float4 av = a4[i4];
        xv.x += alpha * pv[k].x; xv.y += alpha * pv[k].y;
        xv.z += alpha * pv[k].z; xv.w += alpha * pv[k].w;
        rv[k].x -= alpha * av.x; rv[k].y -= alpha * av.y;
        rv[k].z -= alpha * av.z; rv[k].w -= alpha * av.w;
        x4[i4] = xv; r4[i4] = rv[k];
        s += rv[k].x * rv[k].x + rv[k].y * rv[k].y
           + rv[k].z * rv[k].z + rv[k].w * rv[k].w;
    }
    float tot;
    bool last = lastBlockTotal(threadIdx.x, s, b, blockIdx.x, NP_UPD, &tot);
    if (last && threadIdx.x == 0) {
        float rs = d_scal[b];
        int act = d_scal[12 + b] != 0.f;
        d_scal[8 + b] = act ? tot / fmaxf(rs, 1e-12f) : 0.f;  // beta
        d_scal[b] = act ? tot : rs;                            // rs
        __threadfence();
        if (do_p) d_flag[b] = 1;
    }
    if (!do_p) return;
    if (threadIdx.x == 0) {
        while (d_flag[b] == 0) { }
    }
    __syncthreads();
    __threadfence();
    const float beta = d_scal[8 + b];
    const int act = d_scal[12 + b] != 0.f;
    if (act) {
#pragma unroll
        for (int k = 0; k < 4; k++) {
            size_t i4 = base + (size_t)k * 256;
            float4 pn;
            pn.x = rv[k].x + beta * pv[k].x; pn.y = rv[k].y + beta * pv[k].y;
            pn.z = rv[k].z + beta * pv[k].z; pn.w = rv[k].w + beta * pv[k].w;
            p4[i4] = pn;
        }
    }
    __threadfence();
    __syncthreads();
    if (threadIdx.x == 0) {
        int old = atomicAdd(&d_cnt[4 + b], 1);
        if (old == NP_UPD - 1) { d_cnt[4 + b] = 0; d_flag[b] = 0; }
    }
}

// ---------------- host orchestration ----------------
struct Ptrs {
    float *b, *Ap, *t1, *t2, *wreg, *p, *S;
};

extern "C" void kernel_launch(void* const* d_in, const int* in_sizes, int n_in,
                              void* d_out, int out_size)
{
    const float* blurred = (const float*)d_in[0];
    const float* kern    = (const float*)d_in[1];
    const float* dkw     = (const float*)d_in[2];
    const float* dks     = (const float*)d_in[3];
    const float* rkw     = (const float*)d_in[4];
    const float* rks     = (const float*)d_in[5];
    const float* gmmw    = (const float*)d_in[6];
    const float* gmmiv   = (const float*)d_in[7];
    float* x = (float*)d_out;

    Ptrs P;
    cudaGetSymbolAddress((void**)&P.b, d_b);
    cudaGetSymbolAddress((void**)&P.Ap, d_Ap);
    cudaGetSymbolAddress((void**)&P.t1, d_t1);
    cudaGetSymbolAddress((void**)&P.t2, d_t2);
    cudaGetSymbolAddress((void**)&P.wreg, d_wreg);
    cudaGetSymbolAddress((void**)&P.p, d_p);
    cudaGetSymbolAddress((void**)&P.S, d_S);
    void* pcnt;
    cudaGetSymbolAddress(&pcnt, d_cnt);

    const int n_irls = 2, n_cg = 8;
    dim3 gc(6, 12, NBC), bl(32, 8);
    dim3 gb(48, 1, NBC);
    dim3 gu(NP_UPD, BB);

    cudaStream_t s1;
    cudaStreamCreateWithFlags(&s1, cudaStreamNonBlocking);
    cudaEvent_t e0, eA, eB;
    cudaEventCreateWithFlags(&e0, cudaEventDisableTiming);
    cudaEventCreateWithFlags(&eA, cudaEventDisableTiming);
    cudaEventCreateWithFlags(&eB, cudaEventDisableTiming);

    cudaMemsetAsync(pcnt, 0, 8 * sizeof(int), 0);
    autocorr_k<<<1, 256, 0, 0>>>(dks, dkw, rks, rkw);

    // fork: x = blurred on side stream; b-precompute on main
    cudaEventRecord(e0, 0);
    cudaStreamWaitEvent(s1, e0, 0);
    cudaMemcpyAsync(x, blurred, (size_t)NTOT * sizeof(float),
                    cudaMemcpyDeviceToDevice, s1);
    conv9_k<<<gc, bl, 0, 0>>>(blurred, P.t1, P.S);
    border_k<<<gb, 256, 0, 0>>>(blurred, P.t1, dks, dkw, 8);
    corr11_k<<<gc, bl, 0, 0>>>(P.t1, P.b, kern, 1, 0, nullptr);
    cudaEventRecord(eB, s1);
    cudaStreamWaitEvent(0, eB, 0);

    // Aop: side stream runs gmm (optional) + reg term; main runs data chain.
    // mode_final: 1 = fused dot+alpha, 2 = fused residual init + rs
    auto AopL = [&](const float* v, int iter, int mode_final, const float* dv,
                    bool pre_gmm) {
        cudaEventRecord(e0, 0);
        cudaStreamWaitEvent(s1, e0, 0);
        if (pre_gmm)
            gmm_k<<<dim3(12, 12, NBC), dim3(32, 8), 0, s1>>>(x, rks, gmmw, gmmiv);
        if (iter == 0) {
            conv9_k<<<gc, bl, 0, s1>>>(v, P.Ap, P.S + 81);
            border_k<<<gb, 256, 0, s1>>>(v, P.Ap, rks, rkw, IRK);
        } else {
            ata_k<<<gc, bl, 0, s1>>>(v, P.Ap, rks, rkw, P.wreg);
        }
        // main: data chain
        corr11_k<<<gc, bl, 0, 0>>>(v, P.t1, kern, 0, 0, nullptr);
        cudaEventRecord(eA, 0);
        conv9_k<<<gc, bl, 0, 0>>>(P.t1, P.t2, P.S);
        // side: data border concurrent with interior conv9
        cudaStreamWaitEvent(s1, eA, 0);
        border_k<<<gb, 256, 0, s1>>>(P.t1, P.t2, dks, dkw, 8);
        cudaEventRecord(eB, s1);
        // join, then final flipped corr11 accumulates data term into Ap
        cudaStreamWaitEvent(0, eB, 0);
        corr11_k<<<gc, bl, 0, 0>>>(P.t2, P.Ap, kern, 1, mode_final, dv);
    };

    for (int it = 0; it < n_irls; it++) {
        AopL(x, it, 2, nullptr, it == 1);
        for (int s = 0; s < n_cg; s++) {
            AopL(P.p, it, 1, P.p, false);
            update2_k<<<gu, 256, 0, 0>>>(x, s < n_cg - 1 ? 1 : 0);
        }
    }

    cudaEventDestroy(e0);
    cudaEventDestroy(eA);
    cudaEventDestroy(eB);
    cudaStreamDestroy(s1);
}

// round 12
// speedup vs baseline: 1.0589x; 1.0057x over previous
#include <cuda_runtime.h>
#include <math.h>

#define BB 4
#define CC 3
#define HH 384
#define WW 384
#define HWs (HH*WW)
#define NBC 12
#define NTOT (NBC*HWs)
#define NBE (CC*HWs)
#define IRK 16
#define NP_CORR 216   // corr11 blocks per batch (6*12*3)
#define NP_UPD  108   // update2 blocks per batch

// ------------ static device scratch ------------
__device__ float d_b[NTOT];
__device__ float d_r[NTOT];
__device__ float d_p[NTOT];
__device__ float d_Ap[NTOT];
__device__ float d_t1[NTOT];
__device__ float d_t2[NTOT];
__device__ float d_wreg[(size_t)IRK * NTOT];
__device__ float d_part[BB * 512];
__device__ float d_scal[16]; // [0..3]=rs [4..7]=alpha [8..11]=beta [12..15]=active
__device__ float d_S[162];   // [0..80]=S_data  [81..161]=S_reg
__device__ int   d_cnt[8];   // completion counters (self-resetting)
__device__ volatile int d_flag[4];

__device__ __forceinline__ float warpRed(float v) {
#pragma unroll
    for (int o = 16; o > 0; o >>= 1) v += __shfl_down_sync(0xffffffffu, v, o);
    return v;
}

// Block-reduce s, store partial, detect last block of batch b, then cooperatively
// reduce all nblk partials. Returns true on ALL threads of the last block.
__device__ __forceinline__ bool lastBlockTotal(int tid, float s, int b, int slot,
                                               int nblk, float* tot) {
    __shared__ float sm[8];
    __shared__ int lastF;
    float w = warpRed(s);
    if ((tid & 31) == 0) sm[tid >> 5] = w;
    __syncthreads();
    if (tid == 0) {
        float v = 0;
#pragma unroll
        for (int i = 0; i < 8; i++) v += sm[i];
        d_part[b * 512 + slot] = v;
        __threadfence();
        int old = atomicAdd(&d_cnt[b], 1);
        lastF = (old == nblk - 1);
        if (lastF) d_cnt[b] = 0;
    }
    __syncthreads();
    if (!lastF) return false;
    float t = 0;
    for (int i = tid; i < nblk; i += 256) t += d_part[b * 512 + i];
    t = warpRed(t);
    __syncthreads();
    if ((tid & 31) == 0) sm[tid >> 5] = t;
    __syncthreads();
    float v = 0;
#pragma unroll
    for (int i = 0; i < 8; i++) v += sm[i];
    *tot = v;
    return true;
}

// ------- build composed 9x9 kernels S(d) = sum_i kw_i sum_e k_i(e) k_i(e+d) -------
__global__ void autocorr_k(const float* __restrict__ dks, const float* __restrict__ dkw,
                           const float* __restrict__ rks, const float* __restrict__ rkw)
{
    int tid = threadIdx.x;
    if (tid < 162) {
        int which = tid / 81, t = tid % 81;
        const float* ks = which ? rks : dks;
        const float* kw = which ? rkw : dkw;
        int I = which ? 16 : 8;
        int dy = t / 9 - 4, dx = t % 9 - 4;
        float s = 0.f;
        for (int i = 0; i < I; i++) {
            float w = kw[i];
            for (int u = 0; u < 5; u++)
                for (int v = 0; v < 5; v++) {
                    int u2 = u + dy, v2 = v + dx;
                    if (u2 >= 0 && u2 < 5 && v2 >= 0 && v2 < 5)
                        s += w * ks[i * 25 + u * 5 + v] * ks[i * 25 + u2 * 5 + v2];
                }
        }
        d_S[which * 81 + t] = s;
    }
}

// ---------------- 11x11 per-batch correlation, SAME, zero pad ----------------
// 64x32 tile, block (32,8). thread tx covers cols tx and tx+32.
// mode 0: out = acc
// mode 1: out += acc; fused dot(out_new, dv); last block computes alpha/active
// mode 2: Ap = out+acc; rv=b-Ap; r=p=rv; fused rs; last block stores rs
__global__ __launch_bounds__(256)
void corr11_k(const float* __restrict__ in, float* __restrict__ out,
              const float* __restrict__ kern, int flip, int mode,
              const float* __restrict__ dv)
{
    __shared__ float tile[42 * 74];
    __shared__ float sk[121];
    const int bc = blockIdx.z;
    const int bat = bc / CC;
    const float* ip = in + (size_t)bc * HWs;
    const int tid = threadIdx.y * 32 + threadIdx.x;
    if (tid < 121) sk[tid] = kern[bat * 121 + (flip ? 120 - tid : tid)];
    const int X0 = blockIdx.x * 64, Y0 = blockIdx.y * 32;
    for (int k = tid; k < 42 * 74; k += 256) {
        int sy = k / 74, sx = k % 74;
        int gy = Y0 - 5 + sy, gx = X0 - 5 + sx;
        tile[k] = (gy >= 0 && gy < HH && gx >= 0 && gx < WW) ? ip[gy * WW + gx] : 0.f;
    }
    __syncthreads();
    const int ry = threadIdx.y * 4;
    const int tx = threadIdx.x;
    float acc0[4] = {0, 0, 0, 0}, acc1[4] = {0, 0, 0, 0};
#pragma unroll
    for (int a = 0; a < 11; a++) {
        float kc[11];
#pragma unroll
        for (int u = 0; u < 11; u++) kc[u] = sk[u * 11 + a];
#pragma unroll
        for (int rr = 0; rr < 14; rr++) {
            float v0 = tile[(ry + rr) * 74 + tx + a];
            float v1 = tile[(ry + rr) * 74 + tx + 32 + a];
#pragma unroll
            for (int k = 0; k < 4; k++) {
                int u = rr - k;
                if (u >= 0 && u <= 10) {
                    acc0[k] += v0 * kc[u];
                    acc1[k] += v1 * kc[u];
                }
            }
        }
    }
    size_t obase = (size_t)bc * HWs + (size_t)(Y0 + ry) * WW + X0 + tx;
    if (mode == 0) {
#pragma unroll
        for (int k = 0; k < 4; k++) {
            out[obase + (size_t)k * WW] = acc0[k];
            out[obase + (size_t)k * WW + 32] = acc1[k];
        }
        return;
    }
    float s = 0.f;
    if (mode == 1) {
#pragma unroll
        for (int k = 0; k < 4; k++) {
            size_t o = obase + (size_t)k * WW;
            float a0 = out[o] + acc0[k]; out[o] = a0; s += a0 * dv[o];
            size_t o1 = o + 32;
            float a1 = out[o1] + acc1[k]; out[o1] = a1; s += a1 * dv[o1];
        }
    } else {
#pragma unroll
        for (int k = 0; k < 4; k++) {
            size_t o = obase + (size_t)k * WW;
            float a0 = out[o] + acc0[k];
            float rv0 = d_b[o] - a0; d_r[o] = rv0; d_p[o] = rv0; s += rv0 * rv0;
            size_t o1 = o + 32;
            float a1 = out[o1] + acc1[k];
            float rv1 = d_b[o1] - a1; d_r[o1] = rv1; d_p[o1] = rv1; s += rv1 * rv1;
        }
    }
    int slot = (bc % CC) * 72 + blockIdx.y * 6 + blockIdx.x;
    float tot;
    if (lastBlockTotal(tid, s, bat, slot, NP_CORR, &tot)) {
        if (tid == 0) {
            if (mode == 2) {
                d_scal[bat] = tot;                 // rs
            } else {
                float rs = d_scal[bat];
                int act = sqrtf(rs) > 1e-6f;
                d_scal[12 + bat] = act ? 1.f : 0.f;
                d_scal[4 + bat] = act ? rs / fmaxf(tot, 1e-12f) : 0.f;  // alpha
            }
        }
    }
}

// ------- 9x9 composed conv, interior only. 64x32 tile, block (32,8) -------
__global__ __launch_bounds__(256)
void conv9_k(const float* __restrict__ in, float* __restrict__ out,
             const float* __restrict__ S)
{
    __shared__ float tile[40 * 72];
    __shared__ float sk[81];
    const int bc = blockIdx.z;
    const float* ip = in + (size_t)bc * HWs;
    const int tid = threadIdx.y * 32 + threadIdx.x;
    if (tid < 81) sk[tid] = S[tid];
    const int X0 = blockIdx.x * 64, Y0 = blockIdx.y * 32;
    for (int k = tid; k < 40 * 72; k += 256) {
        int sy = k / 72, sx = k % 72;
        int gy = Y0 - 4 + sy, gx = X0 - 4 + sx;
        tile[k] = (gy >= 0 && gy < HH && gx >= 0 && gx < WW) ? ip[gy * WW + gx] : 0.f;
    }
    __syncthreads();
    const int ry = threadIdx.y * 4;
    const int tx = threadIdx.x;
    float acc0[4] = {0, 0, 0, 0}, acc1[4] = {0, 0, 0, 0};
#pragma unroll
    for (int a = 0; a < 9; a++) {
        float kc[9];
#pragma unroll
        for (int u = 0; u < 9; u++) kc[u] = sk[u * 9 + a];
#pragma unroll
        for (int rr = 0; rr < 12; rr++) {
            float v0 = tile[(ry + rr) * 72 + tx + a];
            float v1 = tile[(ry + rr) * 72 + tx + 32 + a];
#pragma unroll
            for (int k = 0; k < 4; k++) {
                int u = rr - k;
                if (u >= 0 && u <= 8) {
                    acc0[k] += v0 * kc[u];
                    acc1[k] += v1 * kc[u];
                }
            }
        }
    }
#pragma unroll
    for (int k = 0; k < 4; k++) {
        int oy = Y0 + ry + k;
        if (oy < 2 || oy >= HH - 2) continue;
        size_t rowo = (size_t)bc * HWs + (size_t)oy * WW;
        int ox0 = X0 + tx, ox1 = ox0 + 32;
        if (ox0 >= 2 && ox0 < WW - 2) out[rowo + ox0] = acc0[k];
        if (ox1 >= 2 && ox1 < WW - 2) out[rowo + ox1] = acc1[k];
    }
}

// ------- exact two-stage sum_i kw_i K_i^T K_i on the 2-pixel border frame -------
__global__ __launch_bounds__(256)
void border_k(const float* __restrict__ in, float* __restrict__ out,
              const float* __restrict__ ks, const float* __restrict__ kw, int I)
{
    __shared__ float vsh[6 * 40];
    __shared__ float tsh[4 * 36];
    __shared__ float sk[IRK * 25];
    __shared__ float skw[IRK];
    const int bc = blockIdx.z;
    const int side = blockIdx.x / 12, seg = blockIdx.x % 12;
    const bool horiz = (side < 2);
    const bool farside = (side & 1);
    const int tid = threadIdx.x;
    for (int k = tid; k < I * 25; k += 256) sk[k] = ks[k];
    if (tid < I) skw[tid] = kw[tid];
    const float* ip = in + (size_t)bc * HWs;
    const int lbase = seg * 32;
    if (tid < 240) {
        int i = tid / 40, j = tid % 40;
        int thin = (farside ? 378 : 0) + i;
        int lng = lbase - 4 + j;
        int gy = horiz ? thin : lng;
        int gx = horiz ? lng : thin;
        vsh[tid] = (gy >= 0 && gy < HH && gx >= 0 && gx < WW) ? ip[gy * WW + gx] : 0.f;
    }
    __syncthreads();
    float acc = 0.f;
    for (int i = 0; i < I; i++) {
        __syncthreads();
        if (tid < 144) {
            int it = tid / 36, jt = tid % 36;
            int glong = lbase - 2 + jt;
            float t = 0.f;
            if (glong >= 0 && glong < 384) {
#pragma unroll
                for (int a = 0; a < 5; a++) {
                    int vi = it + a + (farside ? 0 : -2);
                    if (vi >= 0 && vi < 6) {
#pragma unroll
                        for (int b2 = 0; b2 < 5; b2++) {
                            float kv = horiz ? sk[i * 25 + a * 5 + b2] : sk[i * 25 + b2 * 5 + a];
                            t += kv * vsh[vi * 40 + jt + b2];
                        }
                    }
                }
            }
            tsh[tid] = t;
        }
        __syncthreads();
        if (tid < 64) {
            int io = tid / 32, jo = tid % 32;
            float s = 0.f;
#pragma unroll
            for (int a = 0; a < 5; a++) {
                int it = io + (farside ? 4 : 2) - a;
                if (it >= 0 && it < 4) {
#pragma unroll
                    for (int b2 = 0; b2 < 5; b2++) {
                        int jt = jo + 4 - b2;
                        float kv = horiz ? sk[i * 25 + a * 5 + b2] : sk[i * 25 + b2 * 5 + a];
                        s += kv * tsh[it * 36 + jt];
                    }
                }
            }
            acc += skw[i] * s;
        }
    }
    if (tid < 64) {
        int io = tid / 32, jo = tid % 32;
        int thin = (farside ? 382 : 0) + io;
        int lng = lbase + jo;
        int gy = horiz ? thin : lng;
        int gx = horiz ? lng : thin;
        out[(size_t)bc * HWs + (size_t)gy * WW + gx] = acc;
    }
}

// -------- fused out = sum_i K_i^T ( kw_i * wreg_i * (K_i v) ), iter-1 reg term --------
// 64x32 output tile, block (32,8). t_i double-buffered in smem (36x68 region).
__global__ __launch_bounds__(256)
void ata_k(const float* __restrict__ in, float* __restrict__ out,
           const float* __restrict__ ks, const float* __restrict__ kw,
           const float* __restrict__ wreg)
{
    __shared__ float vt[40 * 72];
    __shared__ float tt[2][36 * 68];
    __shared__ float sk[IRK * 25];
    __shared__ float skw[IRK];
    const int bc = blockIdx.z;
    const float* ip = in + (size_t)bc * HWs;
    const int tid = threadIdx.y * 32 + threadIdx.x;
    for (int k = tid; k < IRK * 25; k += 256) sk[k] = ks[k];
    if (tid < IRK) skw[tid] = kw[tid];
    const int X0 = blockIdx.x * 64, Y0 = blockIdx.y * 32;
    for (int k = tid; k < 40 * 72; k += 256) {
        int sy = k / 72, sx = k % 72;
        int gy = Y0 - 4 + sy, gx = X0 - 4 + sx;
        vt[k] = (gy >= 0 && gy < HH && gx >= 0 && gx < WW) ? ip[gy * WW + gx] : 0.f;
    }
    __syncthreads();
    const int tx = threadIdx.x;
    const int ty = threadIdx.y;
    const int ry = ty * 4;
    float acc0[4] = {0, 0, 0, 0}, acc1[4] = {0, 0, 0, 0};
    int buf = 0;
    for (int i = 0; i < IRK; i++) {
        float kr[25];
#pragma unroll
        for (int k = 0; k < 25; k++) kr[k] = sk[i * 25 + k];
        const float kwv = skw[i];
        // ---- stage 1: weighted t_i over the 36x68 halo region ----
        for (int idx = tid; idx < 36 * 68; idx += 256) {
            int sy = idx / 68, sx = idx % 68;
            int gy = Y0 - 2 + sy, gx = X0 - 2 + sx;
            float o = 0.f;
            if (gy >= 0 && gy < HH && gx >= 0 && gx < WW) {
                float t = 0.f;
#pragma unroll
                for (int u = 0; u < 5; u++)
#pragma unroll
                    for (int v = 0; v < 5; v++)
                        t += kr[u * 5 + v] * vt[(sy + u) * 72 + sx + v];
                o = t * kwv * wreg[((size_t)(bc * IRK + i)) * HWs + (size_t)gy * WW + gx];
            }
            tt[buf][idx] = o;
        }
        __syncthreads();
        // ---- stage 2: adjoint into per-thread accumulators ----
#pragma unroll
        for (int v = 0; v < 5; v++) {
            int c0 = tx + 4 - v;
#pragma unroll
            for (int rr = 0; rr < 8; rr++) {
                float v0 = tt[buf][(ry + rr) * 68 + c0];
                float v1 = tt[buf][(ry + rr) * 68 + c0 + 32];
#pragma unroll
                for (int k = 0; k < 4; k++) {
                    int u = k + 4 - rr;
                    if (u >= 0 && u <= 4) {
                        acc0[k] += v0 * kr[u * 5 + v];
                        acc1[k] += v1 * kr[u * 5 + v];
                    }
                }
            }
        }
        buf ^= 1;
    }
#pragma unroll
    for (int k = 0; k < 4; k++) {
        size_t o = (size_t)bc * HWs + (size_t)(Y0 + ry + k) * WW + X0 + tx;
        out[o] = acc0[k];
        out[o + 32] = acc1[k];
    }
}

// -------- GMM reweighting --------
__global__ __launch_bounds__(256)
void gmm_k(const float* __restrict__ x, const float* __restrict__ rks,
           const float* __restrict__ gw, const float* __restrict__ giv)
{
    __shared__ float tile[36 * 36];
    __shared__ float sk[IRK * 25];
    const int bc = blockIdx.z;
    const float* ip = x + (size_t)bc * HWs;
    const int tid = threadIdx.y * 32 + threadIdx.x;
    for (int k = tid; k < IRK * 25; k += 256) sk[k] = rks[k];
    const int X0 = blockIdx.x * 32, Y0 = blockIdx.y * 32;
    for (int k = tid; k < 36 * 36; k += 256) {
        int sy = k / 36, sx = k % 36;
        int gy = Y0 - 2 + sy, gx = X0 - 2 + sx;
        tile[k] = (gy >= 0 && gy < HH && gx >= 0 && gx < WW) ? ip[gy * WW + gx] : 0.f;
    }
    __syncthreads();
    const int ry = threadIdx.y * 4, tx = threadIdx.x;
    for (int j = 0; j < IRK; j++) {
        float kr[25];
#pragma unroll
        for (int k = 0; k < 25; k++) kr[k] = sk[j * 25 + k];
        float g0 = 0, g1 = 0, g2 = 0, g3 = 0;
#pragma unroll
        for (int v = 0; v < 5; v++) {
#pragma unroll
            for (int rr = 0; rr < 8; rr++) {
                float val = tile[(ry + rr) * 36 + tx + v];
                int u;
                u = rr;     if (u <= 4)           g0 += val * kr[u * 5 + v];
                u = rr - 1; if (u >= 0 && u <= 4) g1 += val * kr[u * 5 + v];
                u = rr - 2; if (u >= 0 && u <= 4) g2 += val * kr[u * 5 + v];
                u = rr - 3; if (u >= 0)           g3 += val * kr[u * 5 + v];
            }
        }
        float iv0 = giv[0 * IRK + j], iv1 = giv[1 * IRK + j], iv2 = giv[2 * IRK + j];
        float c0 = gw[0 * IRK + j] * sqrtf(iv0);
        float c1 = gw[1 * IRK + j] * sqrtf(iv1);
        float c2 = gw[2 * IRK + j] * sqrtf(iv2);
        float gs[4] = {g0, g1, g2, g3};
#pragma unroll
        for (int k2 = 0; k2 < 4; k2++) {
            float gv = gs[k2];
            float p0 = c0 * expf(-0.5f * iv0 * gv * gv);
            float p1 = c1 * expf(-0.5f * iv1 * gv * gv);
            float p2 = c2 * expf(-0.5f * iv2 * gv * gv);
            float num = p0 * iv0 + p1 * iv1 + p2 * iv2;
            float den = p0 + p1 + p2 + 1e-12f;
            d_wreg[((size_t)(bc * IRK + j)) * HWs + (size_t)(Y0 + ry + k2) * WW + X0 + tx] = num / den;
        }
    }
}

// ------- fused CG update: x+=αp, r-=αAp, rs/beta, then (spin) p=r+βp -------
// grid (108, BB) = 432 blocks, all co-resident (256 thr/block, 8 blocks/SM cap).
__global__ void __launch_bounds__(256, 3)
update2_k(float* __restrict__ x, int do_p)
{
    const int b = blockIdx.y;
    const float alpha = d_scal[4 + b];
    float4* x4 = (float4*)x;
    float4* p4 = (float4*)d_p;
    float4* r4 = (float4*)d_r;
    float4* a4 = (float4*)d_Ap;
    size_t base = (size_t)b * (NBE / 4) + (size_t)blockIdx.x * 1024 + threadIdx.x;
    float4 pv[4], rv[4];
    float s = 0.f;
#pragma unroll
    for (int k = 0; k < 4; k++) {
        size_t i4 = base + (size_t)k * 256;
        float4 xv = x4[i4];
        pv[k] = p4[i4]; rv[k] = r4[i4];
        float4 av = a4[i4];
        xv.x += alpha * pv[k].x; xv.y += alpha * pv[k].y;
        xv.z += alpha * pv[k].z; xv.w += alpha * pv[k].w;
        rv[k].x -= alpha * av.x; rv[k].y -= alpha * av.y;
        rv[k].z -= alpha * av.z; rv[k].w -= alpha * av.w;
        x4[i4] = xv; r4[i4] = rv[k];
        s += rv[k].x * rv[k].x + rv[k].y * rv[k].y
           + rv[k].z * rv[k].z + rv[k].w * rv[k].w;
    }
    float tot;
    bool last = lastBlockTotal(threadIdx.x, s, b, blockIdx.x, NP_UPD, &tot);
    if (last && threadIdx.x == 0) {
        float rs = d_scal[b];
        int act = d_scal[12 + b] != 0.f;
        d_scal[8 + b] = act ? tot / fmaxf(rs, 1e-12f) : 0.f;  // beta
        d_scal[b] = act ? tot : rs;                            // rs
        __threadfence();
        if (do_p) d_flag[b] = 1;
    }
    if (!do_p) return;
    if (threadIdx.x == 0) {
        while (d_flag[b] == 0) { }
    }
    __syncthreads();
    __threadfence();
    const float beta = d_scal[8 + b];
    const int act = d_scal[12 + b] != 0.f;
    if (act) {
#pragma unroll
        for (int k = 0; k < 4; k++) {
            size_t i4 = base + (size_t)k * 256;
            float4 pn;
            pn.x = rv[k].x + beta * pv[k].x; pn.y = rv[k].y + beta * pv[k].y;
            pn.z = rv[k].z + beta * pv[k].z; pn.w = rv[k].w + beta * pv[k].w;
            p4[i4] = pn;
        }
    }
    __threadfence();
    __syncthreads();
    if (threadIdx.x == 0) {
        int old = atomicAdd(&d_cnt[4 + b], 1);
        if (old == NP_UPD - 1) { d_cnt[4 + b] = 0; d_flag[b] = 0; }
    }
}

// ---------------- host orchestration ----------------
struct Ptrs {
    float *b, *Ap, *t1, *t2, *wreg, *p, *S;
};

extern "C" void kernel_launch(void* const* d_in, const int* in_sizes, int n_in,
                              void* d_out, int out_size)
{
    const float* blurred = (const float*)d_in[0];
    const float* kern    = (const float*)d_in[1];
    const float* dkw     = (const float*)d_in[2];
    const float* dks     = (const float*)d_in[3];
    const float* rkw     = (const float*)d_in[4];
    const float* rks     = (const float*)d_in[5];
    const float* gmmw    = (const float*)d_in[6];
    const float* gmmiv   = (const float*)d_in[7];
    float* x = (float*)d_out;

    Ptrs P;
    cudaGetSymbolAddress((void**)&P.b, d_b);
    cudaGetSymbolAddress((void**)&P.Ap, d_Ap);
    cudaGetSymbolAddress((void**)&P.t1, d_t1);
    cudaGetSymbolAddress((void**)&P.t2, d_t2);
    cudaGetSymbolAddress((void**)&P.wreg, d_wreg);
    cudaGetSymbolAddress((void**)&P.p, d_p);
    cudaGetSymbolAddress((void**)&P.S, d_S);
    void* pcnt;
    cudaGetSymbolAddress(&pcnt, d_cnt);

    const int n_irls = 2, n_cg = 8;
    dim3 gc(6, 12, NBC), bl(32, 8);
    dim3 gb(48, 1, NBC);
    dim3 gu(NP_UPD, BB);

    cudaStream_t s1;
    cudaStreamCreateWithFlags(&s1, cudaStreamNonBlocking);
    cudaEvent_t e0, eA, eB;
    cudaEventCreateWithFlags(&e0, cudaEventDisableTiming);
    cudaEventCreateWithFlags(&eA, cudaEventDisableTiming);
    cudaEventCreateWithFlags(&eB, cudaEventDisableTiming);

    cudaMemsetAsync(pcnt, 0, 8 * sizeof(int), 0);
    autocorr_k<<<1, 256, 0, 0>>>(dks, dkw, rks, rkw);

    // fork: x = blurred on side stream; b-precompute on main
    cudaEventRecord(e0, 0);
    cudaStreamWaitEvent(s1, e0, 0);
    cudaMemcpyAsync(x, blurred, (size_t)NTOT * sizeof(float),
                    cudaMemcpyDeviceToDevice, s1);
    conv9_k<<<gc, bl, 0, 0>>>(blurred, P.t1, P.S);
    border_k<<<gb, 256, 0, 0>>>(blurred, P.t1, dks, dkw, 8);
    corr11_k<<<gc, bl, 0, 0>>>(P.t1, P.b, kern, 1, 0, nullptr);
    cudaEventRecord(eB, s1);
    cudaStreamWaitEvent(0, eB, 0);

    // Aop: side stream runs gmm (optional) + reg term; main runs data chain.
    // mode_final: 1 = fused dot+alpha, 2 = fused residual init + rs
    auto AopL = [&](const float* v, int iter, int mode_final, const float* dv,
                    bool pre_gmm) {
        cudaEventRecord(e0, 0);
        cudaStreamWaitEvent(s1, e0, 0);
        if (pre_gmm)
            gmm_k<<<dim3(12, 12, NBC), dim3(32, 8), 0, s1>>>(x, rks, gmmw, gmmiv);
        if (iter == 0) {
            conv9_k<<<gc, bl, 0, s1>>>(v, P.Ap, P.S + 81);
            border_k<<<gb, 256, 0, s1>>>(v, P.Ap, rks, rkw, IRK);
        } else {
            ata_k<<<gc, bl, 0, s1>>>(v, P.Ap, rks, rkw, P.wreg);
        }
        // main: data chain
        corr11_k<<<gc, bl, 0, 0>>>(v, P.t1, kern, 0, 0, nullptr);
        cudaEventRecord(eA, 0);
        conv9_k<<<gc, bl, 0, 0>>>(P.t1, P.t2, P.S);
        // side: data border concurrent with interior conv9
        cudaStreamWaitEvent(s1, eA, 0);
        border_k<<<gb, 256, 0, s1>>>(P.t1, P.t2, dks, dkw, 8);
        cudaEventRecord(eB, s1);
        // join, then final flipped corr11 accumulates data term into Ap
        cudaStreamWaitEvent(0, eB, 0);
        corr11_k<<<gc, bl, 0, 0>>>(P.t2, P.Ap, kern, 1, mode_final, dv);
    };

    for (int it = 0; it < n_irls; it++) {
        AopL(x, it, 2, nullptr, it == 1);
        for (int s = 0; s < n_cg; s++) {
            AopL(P.p, it, 1, P.p, false);
            update2_k<<<gu, 256, 0, 0>>>(x, s < n_cg - 1 ? 1 : 0);
        }
    }

    cudaEventDestroy(e0);
    cudaEventDestroy(eA);
    cudaEventDestroy(eB);
    cudaStreamDestroy(s1);
}

// round 13
// speedup vs baseline: 1.0614x; 1.0024x over previous
#include <cuda_runtime.h>
#include <math.h>

#define BB 4
#define CC 3
#define HH 384
#define WW 384
#define HWs (HH*WW)
#define NBC 12
#define NTOT (NBC*HWs)
#define NBE (CC*HWs)
#define IRK 16
#define NP_CORR 216   // corr11 blocks per batch (6*12*3)
#define NP_UPD  108   // update2 blocks per batch

// ------------ static device scratch ------------
__device__ float d_b[NTOT];
__device__ float d_r[NTOT];
__device__ float d_p[NTOT];
__device__ float d_Ap[NTOT];
__device__ float d_t1[NTOT];
__device__ float d_t2[NTOT];
__device__ float d_wreg[(size_t)IRK * NTOT];
__device__ float d_part[BB * 512];
__device__ float d_scal[16]; // [0..3]=rs [4..7]=alpha [8..11]=beta [12..15]=active
__device__ float d_S[162];   // [0..80]=S_data  [81..161]=S_reg
__device__ int   d_cnt[8];   // completion counters (self-resetting)
__device__ volatile int d_flag[4];

__device__ __forceinline__ float warpRed(float v) {
#pragma unroll
    for (int o = 16; o > 0; o >>= 1) v += __shfl_down_sync(0xffffffffu, v, o);
    return v;
}

// Block-reduce s, store partial, detect last block of batch b, then cooperatively
// reduce all nblk partials. Returns true on ALL threads of the last block.
__device__ __forceinline__ bool lastBlockTotal(int tid, float s, int b, int slot,
                                               int nblk, float* tot) {
    __shared__ float sm[8];
    __shared__ int lastF;
    float w = warpRed(s);
    if ((tid & 31) == 0) sm[tid >> 5] = w;
    __syncthreads();
    if (tid == 0) {
        float v = 0;
#pragma unroll
        for (int i = 0; i < 8; i++) v += sm[i];
        d_part[b * 512 + slot] = v;
        __threadfence();
        int old = atomicAdd(&d_cnt[b], 1);
        lastF = (old == nblk - 1);
        if (lastF) d_cnt[b] = 0;
    }
    __syncthreads();
    if (!lastF) return false;
    float t = 0;
    for (int i = tid; i < nblk; i += 256) t += d_part[b * 512 + i];
    t = warpRed(t);
    __syncthreads();
    if ((tid & 31) == 0) sm[tid >> 5] = t;
    __syncthreads();
    float v = 0;
#pragma unroll
    for (int i = 0; i < 8; i++) v += sm[i];
    *tot = v;
    return true;
}

// ------- build composed 9x9 kernels S(d) = sum_i kw_i sum_e k_i(e) k_i(e+d) -------
__global__ void autocorr_k(const float* __restrict__ dks, const float* __restrict__ dkw,
                           const float* __restrict__ rks, const float* __restrict__ rkw)
{
    int tid = threadIdx.x;
    if (tid < 162) {
        int which = tid / 81, t = tid % 81;
        const float* ks = which ? rks : dks;
        const float* kw = which ? rkw : dkw;
        int I = which ? 16 : 8;
        int dy = t / 9 - 4, dx = t % 9 - 4;
        float s = 0.f;
        for (int i = 0; i < I; i++) {
            float w = kw[i];
            for (int u = 0; u < 5; u++)
                for (int v = 0; v < 5; v++) {
                    int u2 = u + dy, v2 = v + dx;
                    if (u2 >= 0 && u2 < 5 && v2 >= 0 && v2 < 5)
                        s += w * ks[i * 25 + u * 5 + v] * ks[i * 25 + u2 * 5 + v2];
                }
        }
        d_S[which * 81 + t] = s;
    }
}

// ---------------- 11x11 per-batch correlation, SAME, zero pad ----------------
// 64x32 tile, block (32,8). thread tx covers cols tx and tx+32.
// mode 0: out = acc
// mode 1: out += acc; fused dot(out_new, dv); last block computes alpha/active
// mode 2: Ap = out+acc; rv=b-Ap; r=p=rv; fused rs; last block stores rs
__global__ __launch_bounds__(256)
void corr11_k(const float* __restrict__ in, float* __restrict__ out,
              const float* __restrict__ kern, int flip, int mode,
              const float* __restrict__ dv)
{
    __shared__ float tile[42 * 74];
    __shared__ float sk[121];
    const int bc = blockIdx.z;
    const int bat = bc / CC;
    const float* ip = in + (size_t)bc * HWs;
    const int tid = threadIdx.y * 32 + threadIdx.x;
    if (tid < 121) sk[tid] = kern[bat * 121 + (flip ? 120 - tid : tid)];
    const int X0 = blockIdx.x * 64, Y0 = blockIdx.y * 32;
    for (int k = tid; k < 42 * 74; k += 256) {
        int sy = k / 74, sx = k % 74;
        int gy = Y0 - 5 + sy, gx = X0 - 5 + sx;
        tile[k] = (gy >= 0 && gy < HH && gx >= 0 && gx < WW) ? ip[gy * WW + gx] : 0.f;
    }
    __syncthreads();
    const int ry = threadIdx.y * 4;
    const int tx = threadIdx.x;
    float acc0[4] = {0, 0, 0, 0}, acc1[4] = {0, 0, 0, 0};
#pragma unroll
    for (int a = 0; a < 11; a++) {
        float kc[11];
#pragma unroll
        for (int u = 0; u < 11; u++) kc[u] = sk[u * 11 + a];
#pragma unroll
        for (int rr = 0; rr < 14; rr++) {
            float v0 = tile[(ry + rr) * 74 + tx + a];
            float v1 = tile[(ry + rr) * 74 + tx + 32 + a];
#pragma unroll
            for (int k = 0; k < 4; k++) {
                int u = rr - k;
                if (u >= 0 && u <= 10) {
                    acc0[k] += v0 * kc[u];
                    acc1[k] += v1 * kc[u];
                }
            }
        }
    }
    size_t obase = (size_t)bc * HWs + (size_t)(Y0 + ry) * WW + X0 + tx;
    if (mode == 0) {
#pragma unroll
        for (int k = 0; k < 4; k++) {
            out[obase + (size_t)k * WW] = acc0[k];
            out[obase + (size_t)k * WW + 32] = acc1[k];
        }
        return;
    }
    float s = 0.f;
    if (mode == 1) {
#pragma unroll
        for (int k = 0; k < 4; k++) {
            size_t o = obase + (size_t)k * WW;
            float a0 = out[o] + acc0[k]; out[o] = a0; s += a0 * dv[o];
            size_t o1 = o + 32;
            float a1 = out[o1] + acc1[k]; out[o1] = a1; s += a1 * dv[o1];
        }
    } else {
#pragma unroll
        for (int k = 0; k < 4; k++) {
            size_t o = obase + (size_t)k * WW;
            float a0 = out[o] + acc0[k];
            float rv0 = d_b[o] - a0; d_r[o] = rv0; d_p[o] = rv0; s += rv0 * rv0;
            size_t o1 = o + 32;
            float a1 = out[o1] + acc1[k];
            float rv1 = d_b[o1] - a1; d_r[o1] = rv1; d_p[o1] = rv1; s += rv1 * rv1;
        }
    }
    int slot = (bc % CC) * 72 + blockIdx.y * 6 + blockIdx.x;
    float tot;
    if (lastBlockTotal(tid, s, bat, slot, NP_CORR, &tot)) {
        if (tid == 0) {
            if (mode == 2) {
                d_scal[bat] = tot;                 // rs
            } else {
                float rs = d_scal[bat];
                int act = sqrtf(rs) > 1e-6f;
                d_scal[12 + bat] = act ? 1.f : 0.f;
                d_scal[4 + bat] = act ? rs / fmaxf(tot, 1e-12f) : 0.f;  // alpha
            }
        }
    }
}

// ------- 9x9 composed conv, interior only. 64x32 tile, block (32,8) -------
__global__ __launch_bounds__(256)
void conv9_k(const float* __restrict__ in, float* __restrict__ out,
             const float* __restrict__ S)
{
    __shared__ float tile[40 * 72];
    __shared__ float sk[81];
    const int bc = blockIdx.z;
    const float* ip = in + (size_t)bc * HWs;
    const int tid = threadIdx.y * 32 + threadIdx.x;
    if (tid < 81) sk[tid] = S[tid];
    const int X0 = blockIdx.x * 64, Y0 = blockIdx.y * 32;
    for (int k = tid; k < 40 * 72; k += 256) {
        int sy = k / 72, sx = k % 72;
        int gy = Y0 - 4 + sy, gx = X0 - 4 + sx;
        tile[k] = (gy >= 0 && gy < HH && gx >= 0 && gx < WW) ? ip[gy * WW + gx] : 0.f;
    }
    __syncthreads();
    const int ry = threadIdx.y * 4;
    const int tx = threadIdx.x;
    float acc0[4] = {0, 0, 0, 0}, acc1[4] = {0, 0, 0, 0};
#pragma unroll
    for (int a = 0; a < 9; a++) {
        float kc[9];
#pragma unroll
        for (int u = 0; u < 9; u++) kc[u] = sk[u * 9 + a];
#pragma unroll
        for (int rr = 0; rr < 12; rr++) {
            float v0 = tile[(ry + rr) * 72 + tx + a];
            float v1 = tile[(ry + rr) * 72 + tx + 32 + a];
#pragma unroll
            for (int k = 0; k < 4; k++) {
                int u = rr - k;
                if (u >= 0 && u <= 8) {
                    acc0[k] += v0 * kc[u];
                    acc1[k] += v1 * kc[u];
                }
            }
        }
    }
#pragma unroll
    for (int k = 0; k < 4; k++) {
        int oy = Y0 + ry + k;
        if (oy < 2 || oy >= HH - 2) continue;
        size_t rowo = (size_t)bc * HWs + (size_t)oy * WW;
        int ox0 = X0 + tx, ox1 = ox0 + 32;
        if (ox0 >= 2 && ox0 < WW - 2) out[rowo + ox0] = acc0[k];
        if (ox1 >= 2 && ox1 < WW - 2) out[rowo + ox1] = acc1[k];
    }
}

// ------- exact two-stage sum_i kw_i K_i^T K_i on the 2-pixel border frame -------
__global__ __launch_bounds__(256)
void border_k(const float* __restrict__ in, float* __restrict__ out,
              const float* __restrict__ ks, const float* __restrict__ kw, int I)
{
    __shared__ float vsh[6 * 40];
    __shared__ float tsh[4 * 36];
    __shared__ float sk[IRK * 25];
    __shared__ float skw[IRK];
    const int bc = blockIdx.z;
    const int side = blockIdx.x / 12, seg = blockIdx.x % 12;
    const bool horiz = (side < 2);
    const bool farside = (side & 1);
    const int tid = threadIdx.x;
    for (int k = tid; k < I * 25; k += 256) sk[k] = ks[k];
    if (tid < I) skw[tid] = kw[tid];
    const float* ip = in + (size_t)bc * HWs;
    const int lbase = seg * 32;
    if (tid < 240) {
        int i = tid / 40, j = tid % 40;
        int thin = (farside ? 378 : 0) + i;
        int lng = lbase - 4 + j;
        int gy = horiz ? thin : lng;
        int gx = horiz ? lng : thin;
        vsh[tid] = (gy >= 0 && gy < HH && gx >= 0 && gx < WW) ? ip[gy * WW + gx] : 0.f;
    }
    __syncthreads();
    float acc = 0.f;
    for (int i = 0; i < I; i++) {
        __syncthreads();
        if (tid < 144) {
            int it = tid / 36, jt = tid % 36;
            int glong = lbase - 2 + jt;
            float t = 0.f;
            if (glong >= 0 && glong < 384) {
#pragma unroll
                for (int a = 0; a < 5; a++) {
                    int vi = it + a + (farside ? 0 : -2);
                    if (vi >= 0 && vi < 6) {
#pragma unroll
                        for (int b2 = 0; b2 < 5; b2++) {
                            float kv = horiz ? sk[i * 25 + a * 5 + b2] : sk[i * 25 + b2 * 5 + a];
                            t += kv * vsh[vi * 40 + jt + b2];
                        }
                    }
                }
            }
            tsh[tid] = t;
        }
        __syncthreads();
        if (tid < 64) {
            int io = tid / 32, jo = tid % 32;
            float s = 0.f;
#pragma unroll
            for (int a = 0; a < 5; a++) {
                int it = io + (farside ? 4 : 2) - a;
                if (it >= 0 && it < 4) {
#pragma unroll
                    for (int b2 = 0; b2 < 5; b2++) {
                        int jt = jo + 4 - b2;
                        float kv = horiz ? sk[i * 25 + a * 5 + b2] : sk[i * 25 + b2 * 5 + a];
                        s += kv * tsh[it * 36 + jt];
                    }
                }
            }
            acc += skw[i] * s;
        }
    }
    if (tid < 64) {
        int io = tid / 32, jo = tid % 32;
        int thin = (farside ? 382 : 0) + io;
        int lng = lbase + jo;
        int gy = horiz ? thin : lng;
        int gx = horiz ? lng : thin;
        out[(size_t)bc * HWs + (size_t)gy * WW + gx] = acc;
    }
}

// -------- fused out = sum_i K_i^T ( kw_i * wreg_i * (K_i v) ), iter-1 reg term --------
// 64x32 output tile, block (32,8). t_i double-buffered in smem (36x68 region).
__global__ __launch_bounds__(256)
void ata_k(const float* __restrict__ in, float* __restrict__ out,
           const float* __restrict__ ks, const float* __restrict__ kw,
           const float* __restrict__ wreg)
{
    __shared__ float vt[40 * 72];
    __shared__ float tt[2][36 * 68];
    __shared__ float sk[IRK * 25];
    __shared__ float skw[IRK];
    const int bc = blockIdx.z;
    const float* ip = in + (size_t)bc * HWs;
    const int tid = threadIdx.y * 32 + threadIdx.x;
    for (int k = tid; k < IRK * 25; k += 256) sk[k] = ks[k];
    if (tid < IRK) skw[tid] = kw[tid];
    const int X0 = blockIdx.x * 64, Y0 = blockIdx.y * 32;
    for (int k = tid; k < 40 * 72; k += 256) {
        int sy = k / 72, sx = k % 72;
        int gy = Y0 - 4 + sy, gx = X0 - 4 + sx;
        vt[k] = (gy >= 0 && gy < HH && gx >= 0 && gx < WW) ? ip[gy * WW + gx] : 0.f;
    }
    __syncthreads();
    const int tx = threadIdx.x;
    const int ty = threadIdx.y;
    const int ry = ty * 4;
    float acc0[4] = {0, 0, 0, 0}, acc1[4] = {0, 0, 0, 0};
    int buf = 0;
    for (int i = 0; i < IRK; i++) {
        float kr[25];
#pragma unroll
        for (int k = 0; k < 25; k++) kr[k] = sk[i * 25 + k];
        const float kwv = skw[i];
        // ---- stage 1: weighted t_i over the 36x68 halo region ----
        for (int idx = tid; idx < 36 * 68; idx += 256) {
            int sy = idx / 68, sx = idx % 68;
            int gy = Y0 - 2 + sy, gx = X0 - 2 + sx;
            float o = 0.f;
            if (gy >= 0 && gy < HH && gx >= 0 && gx < WW) {
                float t = 0.f;
#pragma unroll
                for (int u = 0; u < 5; u++)
#pragma unroll
                    for (int v = 0; v < 5; v++)
                        t += kr[u * 5 + v] * vt[(sy + u) * 72 + sx + v];
                o = t * kwv * wreg[((size_t)(bc * IRK + i)) * HWs + (size_t)gy * WW + gx];
            }
            tt[buf][idx] = o;
        }
        __syncthreads();
        // ---- stage 2: adjoint into per-thread accumulators ----
#pragma unroll
        for (int v = 0; v < 5; v++) {
            int c0 = tx + 4 - v;
#pragma unroll
            for (int rr = 0; rr < 8; rr++) {
                float v0 = tt[buf][(ry + rr) * 68 + c0];
                float v1 = tt[buf][(ry + rr) * 68 + c0 + 32];
#pragma unroll
                for (int k = 0; k < 4; k++) {
                    int u = k + 4 - rr;
                    if (u >= 0 && u <= 4) {
                        acc0[k] += v0 * kr[u * 5 + v];
                        acc1[k] += v1 * kr[u * 5 + v];
                    }
                }
            }
        }
        buf ^= 1;
    }
#pragma unroll
    for (int k = 0; k < 4; k++) {
        size_t o = (size_t)bc * HWs + (size_t)(Y0 + ry + k) * WW + X0 + tx;
        out[o] = acc0[k];
        out[o + 32] = acc1[k];
    }
}

// -------- GMM reweighting --------
__global__ __launch_bounds__(256)
void gmm_k(const float* __restrict__ x, const float* __restrict__ rks,
           const float* __restrict__ gw, const float* __restrict__ giv)
{
    __shared__ float tile[36 * 36];
    __shared__ float sk[IRK * 25];
    const int bc = blockIdx.z;
    const float* ip = x + (size_t)bc * HWs;
    const int tid = threadIdx.y * 32 + threadIdx.x;
    for (int k = tid; k < IRK * 25; k += 256) sk[k] = rks[k];
    const int X0 = blockIdx.x * 32, Y0 = blockIdx.y * 32;
    for (int k = tid; k < 36 * 36; k += 256) {
        int sy = k / 36, sx = k % 36;
        int gy = Y0 - 2 + sy, gx = X0 - 2 + sx;
        tile[k] = (gy >= 0 && gy < HH && gx >= 0 && gx < WW) ? ip[gy * WW + gx] : 0.f;
    }
    __syncthreads();
    const int ry = threadIdx.y * 4, tx = threadIdx.x;
    for (int j = 0; j < IRK; j++) {
        float kr[25];
#pragma unroll
        for (int k = 0; k < 25; k++) kr[k] = sk[j * 25 + k];
        float g0 = 0, g1 = 0, g2 = 0, g3 = 0;
#pragma unroll
        for (int v = 0; v < 5; v++) {
#pragma unroll
            for (int rr = 0; rr < 8; rr++) {
                float val = tile[(ry + rr) * 36 + tx + v];
                int u;
                u = rr;     if (u <= 4)           g0 += val * kr[u * 5 + v];
                u = rr - 1; if (u >= 0 && u <= 4) g1 += val * kr[u * 5 + v];
                u = rr - 2; if (u >= 0 && u <= 4) g2 += val * kr[u * 5 + v];
                u = rr - 3; if (u >= 0)           g3 += val * kr[u * 5 + v];
            }
        }
        float iv0 = giv[0 * IRK + j], iv1 = giv[1 * IRK + j], iv2 = giv[2 * IRK + j];
        float c0 = gw[0 * IRK + j] * sqrtf(iv0);
        float c1 = gw[1 * IRK + j] * sqrtf(iv1);
        float c2 = gw[2 * IRK + j] * sqrtf(iv2);
        float gs[4] = {g0, g1, g2, g3};
#pragma unroll
        for (int k2 = 0; k2 < 4; k2++) {
            float gv = gs[k2];
            float p0 = c0 * expf(-0.5f * iv0 * gv * gv);
            float p1 = c1 * expf(-0.5f * iv1 * gv * gv);
            float p2 = c2 * expf(-0.5f * iv2 * gv * gv);
            float num = p0 * iv0 + p1 * iv1 + p2 * iv2;
            float den = p0 + p1 + p2 + 1e-12f;
            d_wreg[((size_t)(bc * IRK + j)) * HWs + (size_t)(Y0 + ry + k2) * WW + X0 + tx] = num / den;
        }
    }
}

// ------- fused CG update: x+=αp, r-=αAp, rs/beta, then (spin) p=r+βp -------
// grid (108, BB) = 432 blocks, all co-resident (256 thr/block, 8 blocks/SM cap).
__global__ void __launch_bounds__(256, 3)
update2_k(float* __restrict__ x, int do_p)
{
    const int b = blockIdx.y;
    const float alpha = d_scal[4 + b];
    float4* x4 = (float4*)x;
    float4* p4 = (float4*)d_p;
    float4* r4 = (float4*)d_r;
    float4* a4 = (float4*)d_Ap;
    size_t base = (size_t)b * (NBE / 4) + (size_t)blockIdx.x * 1024 + threadIdx.x;
    float4 pv[4], rv[4];
    float s = 0.f;
#pragma unroll
    for (int k = 0; k < 4; k++) {
        size_t i4 = base + (size_t)k * 256;
        float4 xv = x4[i4];
        pv[k] = p4[i4]; rv[k] = r4[i4];
        float4 av = a4[i4];
        xv.x += alpha * pv[k].x; xv.y += alpha * pv[k].y;
        xv.z += alpha * pv[k].z; xv.w += alpha * pv[k].w;
        rv[k].x -= alpha * av.x; rv[k].y -= alpha * av.y;
        rv[k].z -= alpha * av.z; rv[k].w -= alpha * av.w;
        x4[i4] = xv; r4[i4] = rv[k];
        s += rv[k].x * rv[k].x + rv[k].y * rv[k].y
           + rv[k].z * rv[k].z + rv[k].w * rv[k].w;
    }
    float tot;
    bool last = lastBlockTotal(threadIdx.x, s, b, blockIdx.x, NP_UPD, &tot);
    if (last && threadIdx.x == 0) {
        float rs = d_scal[b];
        int act = d_scal[12 + b] != 0.f;
        d_scal[8 + b] = act ? tot / fmaxf(rs, 1e-12f) : 0.f;  // beta
        d_scal[b] = act ? tot : rs;                            // rs
        __threadfence();
        if (do_p) d_flag[b] = 1;
    }
    if (!do_p) return;
    if (threadIdx.x == 0) {
        while (d_flag[b] == 0) { }
    }
    __syncthreads();
    __threadfence();
    const float beta = d_scal[8 + b];
    const int act = d_scal[12 + b] != 0.f;
    if (act) {
#pragma unroll
        for (int k = 0; k < 4; k++) {
            size_t i4 = base + (size_t)k * 256;
            float4 pn;
            pn.x = rv[k].x + beta * pv[k].x; pn.y = rv[k].y + beta * pv[k].y;
            pn.z = rv[k].z + beta * pv[k].z; pn.w = rv[k].w + beta * pv[k].w;
            p4[i4] = pn;
        }
    }
    __threadfence();
    __syncthreads();
    if (threadIdx.x == 0) {
        int old = atomicAdd(&d_cnt[4 + b], 1);
        if (old == NP_UPD - 1) { d_cnt[4 + b] = 0; d_flag[b] = 0; }
    }
}

// ---------------- host orchestration ----------------
struct Ptrs {
    float *b, *Ap, *t1, *t2, *wreg, *p, *S;
};

extern "C" void kernel_launch(void* const* d_in, const int* in_sizes, int n_in,
                              void* d_out, int out_size)
{
    const float* blurred = (const float*)d_in[0];
    const float* kern    = (const float*)d_in[1];
    const float* dkw     = (const float*)d_in[2];
    const float* dks     = (const float*)d_in[3];
    const float* rkw     = (const float*)d_in[4];
    const float* rks     = (const float*)d_in[5];
    const float* gmmw    = (const float*)d_in[6];
    const float* gmmiv   = (const float*)d_in[7];
    float* x = (float*)d_out;

    Ptrs P;
    cudaGetSymbolAddress((void**)&P.b, d_b);
    cudaGetSymbolAddress((void**)&P.Ap, d_Ap);
    cudaGetSymbolAddress((void**)&P.t1, d_t1);
    cudaGetSymbolAddress((void**)&P.t2, d_t2);
    cudaGetSymbolAddress((void**)&P.wreg, d_wreg);
    cudaGetSymbolAddress((void**)&P.p, d_p);
    cudaGetSymbolAddress((void**)&P.S, d_S);
    void* pcnt;
    cudaGetSymbolAddress(&pcnt, d_cnt);

    const int n_irls = 2, n_cg = 8;
    dim3 gc(6, 12, NBC), bl(32, 8);
    dim3 gb(48, 1, NBC);
    dim3 gu(NP_UPD, BB);

    cudaStream_t s1;
    cudaStreamCreateWithFlags(&s1, cudaStreamNonBlocking);
    cudaEvent_t e0, eA, eB;
    cudaEventCreateWithFlags(&e0, cudaEventDisableTiming);
    cudaEventCreateWithFlags(&eA, cudaEventDisableTiming);
    cudaEventCreateWithFlags(&eB, cudaEventDisableTiming);

    cudaMemsetAsync(pcnt, 0, 8 * sizeof(int), 0);
    autocorr_k<<<1, 256, 0, 0>>>(dks, dkw, rks, rkw);

    // fork: x = blurred on side stream; b-precompute on main
    cudaEventRecord(e0, 0);
    cudaStreamWaitEvent(s1, e0, 0);
    cudaMemcpyAsync(x, blurred, (size_t)NTOT * sizeof(float),
                    cudaMemcpyDeviceToDevice, s1);
    conv9_k<<<gc, bl, 0, 0>>>(blurred, P.t1, P.S);
    border_k<<<gb, 256, 0, 0>>>(blurred, P.t1, dks, dkw, 8);
    corr11_k<<<gc, bl, 0, 0>>>(P.t1, P.b, kern, 1, 0, nullptr);
    cudaEventRecord(eB, s1);
    cudaStreamWaitEvent(0, eB, 0);

    // Aop: side stream runs gmm (optional) + reg term; main runs data chain.
    // mode_final: 1 = fused dot+alpha, 2 = fused residual init + rs
    auto AopL = [&](const float* v, int iter, int mode_final, const float* dv,
                    bool pre_gmm) {
        cudaEventRecord(e0, 0);
        cudaStreamWaitEvent(s1, e0, 0);
        if (pre_gmm)
            gmm_k<<<dim3(12, 12, NBC), dim3(32, 8), 0, s1>>>(x, rks, gmmw, gmmiv);
        if (iter == 0) {
            conv9_k<<<gc, bl, 0, s1>>>(v, P.Ap, P.S + 81);
            border_k<<<gb, 256, 0, s1>>>(v, P.Ap, rks, rkw, IRK);
        } else {
            ata_k<<<gc, bl, 0, s1>>>(v, P.Ap, rks, rkw, P.wreg);
        }
        // main: data chain
        corr11_k<<<gc, bl, 0, 0>>>(v, P.t1, kern, 0, 0, nullptr);
        cudaEventRecord(eA, 0);
        conv9_k<<<gc, bl, 0, 0>>>(P.t1, P.t2, P.S);
        // side: data border concurrent with interior conv9
        cudaStreamWaitEvent(s1, eA, 0);
        border_k<<<gb, 256, 0, s1>>>(P.t1, P.t2, dks, dkw, 8);
        cudaEventRecord(eB, s1);
        // join, then final flipped corr11 accumulates data term into Ap
        cudaStreamWaitEvent(0, eB, 0);
        corr11_k<<<gc, bl, 0, 0>>>(P.t2, P.Ap, kern, 1, mode_final, dv);
    };

    for (int it = 0; it < n_irls; it++) {
        AopL(x, it, 2, nullptr, it == 1);
        for (int s = 0; s < n_cg; s++) {
            AopL(P.p, it, 1, P.p, false);
            update2_k<<<gu, 256, 0, 0>>>(x, s < n_cg - 1 ? 1 : 0);
        }
    }

    cudaEventDestroy(e0);
    cudaEventDestroy(eA);
    cudaEventDestroy(eB);
    cudaStreamDestroy(s1);
}